// round 3
// baseline (speedup 1.0000x reference)
#include <cuda_runtime.h>
#include <cstdint>

#define NN      50000
#define F       64
#define F4      16          // float4 per node row
#define OUTF    256
#define BM      128
#define BN      128
#define BK      16

// -------- scratch (device globals; no allocation allowed) --------
__device__ float g_dsqrt[NN];
__device__ int   g_deg[NN];
__device__ float g_agg[NN * F];
__device__ float g_xs[NN * F];
__device__ float g_Xt[(size_t)NN * OUTF];   // [N, 256] = concat(X0..X3)

// -------- degree --------
__global__ void k_zero_deg(int n) {
    int i = blockIdx.x * blockDim.x + threadIdx.x;
    if (i < n) g_deg[i] = 0;
}

__global__ void k_hist(const int* __restrict__ dst, int E) {
    int i = blockIdx.x * blockDim.x + threadIdx.x;
    if (i < E) atomicAdd(&g_deg[dst[i]], 1);
}

__global__ void k_dsqrt(int n) {
    int i = blockIdx.x * blockDim.x + threadIdx.x;
    if (i < n) {
        int d = g_deg[i];
        if (d < 1) d = 1;
        g_dsqrt[i] = rsqrtf((float)d);
    }
}

// -------- prep: Xt[:,0:64]=X0, xs = X0*dsqrt, agg = 0 --------
__global__ void k_prep(const float* __restrict__ x0, int n16) {
    int i = blockIdx.x * blockDim.x + threadIdx.x;
    if (i >= n16) return;
    int node = i >> 4;
    int q = i & 15;
    float ds = g_dsqrt[node];
    float4 v = reinterpret_cast<const float4*>(x0)[i];
    reinterpret_cast<float4*>(g_Xt + (size_t)node * OUTF)[q] = v;
    reinterpret_cast<float4*>(g_xs)[i] = make_float4(v.x * ds, v.y * ds, v.z * ds, v.w * ds);
    reinterpret_cast<float4*>(g_agg)[i] = make_float4(0.f, 0.f, 0.f, 0.f);
}

// -------- scatter: agg[dst] += xs[src], vectorized red.v4 --------
// Warp handles 2 edges per iter: lanes 0-15 -> edge e0 (float4 q), lanes 16-31 -> edge e1.
__global__ void k_scatter(const int* __restrict__ src, const int* __restrict__ dst, int E) {
    int lane = threadIdx.x & 31;
    int gw = (blockIdx.x * blockDim.x + threadIdx.x) >> 5;
    int nwarps = (gridDim.x * blockDim.x) >> 5;
    int half = lane >> 4;
    int q = lane & 15;
    for (int e = gw * 2 + half; e < E; e += nwarps * 2) {
        int s = src[e];
        int d = dst[e];
        float4 v = reinterpret_cast<const float4*>(g_xs + (size_t)s * F)[q];
        float* p = g_agg + (size_t)d * F + q * 4;
        asm volatile("red.global.add.v4.f32 [%0], {%1,%2,%3,%4};"
                     :: "l"(p), "f"(v.x), "f"(v.y), "f"(v.z), "f"(v.w) : "memory");
    }
}

// -------- combine: Chebyshev recurrence, writes Xt block STEP --------
// STEP==1: X1 = -re*L + (re-1)*X0
// STEP>=2: Xs = -2re*L + 2(re-1)*X_{s-1} - X_{s-2},  L = agg*dsqrt
template <int STEP>
__global__ void k_combine(const float* __restrict__ x0, const float* __restrict__ lam, int n16) {
    int i = blockIdx.x * blockDim.x + threadIdx.x;
    if (i >= n16) return;
    int node = i >> 4;
    int q = i & 15;
    float ds = g_dsqrt[node];
    float re = 2.0f / lam[0];
    float4 ag = reinterpret_cast<const float4*>(g_agg)[i];
    float4 out;
    if (STEP == 1) {
        float4 c = reinterpret_cast<const float4*>(x0)[i];
        float ca = -re, cc = re - 1.0f;
        out.x = ca * (ag.x * ds) + cc * c.x;
        out.y = ca * (ag.y * ds) + cc * c.y;
        out.z = ca * (ag.z * ds) + cc * c.z;
        out.w = ca * (ag.w * ds) + cc * c.w;
    } else {
        float4 c = reinterpret_cast<const float4*>(g_Xt + (size_t)node * OUTF + (STEP - 1) * F)[q];
        float4 p = reinterpret_cast<const float4*>(g_Xt + (size_t)node * OUTF + (STEP - 2) * F)[q];
        float ca = -2.0f * re, cc = 2.0f * (re - 1.0f);
        out.x = ca * (ag.x * ds) + cc * c.x - p.x;
        out.y = ca * (ag.y * ds) + cc * c.y - p.y;
        out.z = ca * (ag.z * ds) + cc * c.z - p.z;
        out.w = ca * (ag.w * ds) + cc * c.w - p.w;
    }
    reinterpret_cast<float4*>(g_Xt + (size_t)node * OUTF + STEP * F)[q] = out;
    if (STEP < 3) {
        reinterpret_cast<float4*>(g_xs)[i] =
            make_float4(out.x * ds, out.y * ds, out.z * ds, out.w * ds);
        reinterpret_cast<float4*>(g_agg)[i] = make_float4(0.f, 0.f, 0.f, 0.f);
    }
}

// -------- GEMM: out = relu(Xt @ W + b), A=[M,256], B=[256,256] --------
__global__ __launch_bounds__(256, 2)
void k_gemm(const float* __restrict__ Wm, const float* __restrict__ bias,
            float* __restrict__ out, int M) {
    __shared__ __align__(16) float As[BK][BM + 4];
    __shared__ __align__(16) float Bs[BK][BN];
    int bm = blockIdx.x * BM;
    int bn = blockIdx.y * BN;
    int tid = threadIdx.x;
    int tx = tid & 15;
    int ty = tid >> 4;

    float acc[8][8];
#pragma unroll
    for (int ii = 0; ii < 8; ii++)
#pragma unroll
        for (int jj = 0; jj < 8; jj++) acc[ii][jj] = 0.f;

    const float* A = g_Xt;
    for (int k0 = 0; k0 < OUTF; k0 += BK) {
#pragma unroll
        for (int t = 0; t < 2; t++) {
            int id = tid * 2 + t;
            // A tile: 128 rows x 16 k
            int ar = id >> 2;
            int ac = (id & 3) * 4;
            float4 av;
            if (bm + ar < M)
                av = *reinterpret_cast<const float4*>(A + (size_t)(bm + ar) * OUTF + k0 + ac);
            else
                av = make_float4(0.f, 0.f, 0.f, 0.f);
            As[ac + 0][ar] = av.x;
            As[ac + 1][ar] = av.y;
            As[ac + 2][ar] = av.z;
            As[ac + 3][ar] = av.w;
            // B tile: 16 k x 128 cols
            int br = id >> 5;
            int bc = (id & 31) * 4;
            float4 bv = *reinterpret_cast<const float4*>(Wm + (size_t)(k0 + br) * OUTF + bn + bc);
            *reinterpret_cast<float4*>(&Bs[br][bc]) = bv;
        }
        __syncthreads();
#pragma unroll
        for (int kk = 0; kk < BK; kk++) {
            float4 a0 = *reinterpret_cast<const float4*>(&As[kk][ty * 8]);
            float4 a1 = *reinterpret_cast<const float4*>(&As[kk][ty * 8 + 4]);
            float4 b0 = *reinterpret_cast<const float4*>(&Bs[kk][tx * 8]);
            float4 b1 = *reinterpret_cast<const float4*>(&Bs[kk][tx * 8 + 4]);
            float a[8] = {a0.x, a0.y, a0.z, a0.w, a1.x, a1.y, a1.z, a1.w};
            float b[8] = {b0.x, b0.y, b0.z, b0.w, b1.x, b1.y, b1.z, b1.w};
#pragma unroll
            for (int ii = 0; ii < 8; ii++)
#pragma unroll
                for (int jj = 0; jj < 8; jj++) acc[ii][jj] += a[ii] * b[jj];
        }
        __syncthreads();
    }

#pragma unroll
    for (int ii = 0; ii < 8; ii++) {
        int row = bm + ty * 8 + ii;
        if (row >= M) continue;
#pragma unroll
        for (int jj = 0; jj < 8; jj += 4) {
            int col = bn + tx * 8 + jj;
            float4 bb = *reinterpret_cast<const float4*>(bias + col);
            float4 r;
            r.x = fmaxf(acc[ii][jj + 0] + bb.x, 0.f);
            r.y = fmaxf(acc[ii][jj + 1] + bb.y, 0.f);
            r.z = fmaxf(acc[ii][jj + 2] + bb.z, 0.f);
            r.w = fmaxf(acc[ii][jj + 3] + bb.w, 0.f);
            *reinterpret_cast<float4*>(out + (size_t)row * OUTF + col) = r;
        }
    }
}

extern "C" void kernel_launch(void* const* d_in, const int* in_sizes, int n_in,
                              void* d_out, int out_size) {
    const float* signal = (const float*)d_in[0];
    const int*   src    = (const int*)d_in[1];
    const int*   dst    = (const int*)d_in[2];
    const float* lam    = (const float*)d_in[3];
    const float* Wm     = (const float*)d_in[4];
    const float* bias   = (const float*)d_in[5];
    float*       out    = (float*)d_out;

    int N = in_sizes[0] / F;
    int E = in_sizes[1];
    int n16 = N * F4;

    k_zero_deg<<<(N + 255) / 256, 256>>>(N);
    k_hist<<<(E + 255) / 256, 256>>>(dst, E);
    k_dsqrt<<<(N + 255) / 256, 256>>>(N);
    k_prep<<<(n16 + 255) / 256, 256>>>(signal, n16);

    k_scatter<<<2048, 256>>>(src, dst, E);
    k_combine<1><<<(n16 + 255) / 256, 256>>>(signal, lam, n16);
    k_scatter<<<2048, 256>>>(src, dst, E);
    k_combine<2><<<(n16 + 255) / 256, 256>>>(signal, lam, n16);
    k_scatter<<<2048, 256>>>(src, dst, E);
    k_combine<3><<<(n16 + 255) / 256, 256>>>(signal, lam, n16);

    dim3 g((N + BM - 1) / BM, OUTF / BN);
    k_gemm<<<g, 256>>>(Wm, bias, out, N);
}

// round 5
// speedup vs baseline: 1.3038x; 1.3038x over previous
#include <cuda_runtime.h>
#include <cstdint>

#define NN      50000
#define F       64
#define F4      16
#define OUTF    256

// -------- scratch (device globals; no allocation allowed) --------
__device__ float g_dsqrt[NN];
__device__ int   g_deg[NN];
__device__ float g_agg[NN * F];
__device__ float g_xs[NN * F];
__device__ float g_Xt[(size_t)NN * OUTF];        // [N, 256] = concat(X0..X3)
__device__ uint32_t g_Wt[OUTF * OUTF];           // W [K,N] as tf32 bits

// ================= graph propagation (unchanged, known-good) =================

__global__ void k_zero_deg(int n) {
    int i = blockIdx.x * blockDim.x + threadIdx.x;
    if (i < n) g_deg[i] = 0;
}

__global__ void k_hist(const int* __restrict__ dst, int E) {
    int i = blockIdx.x * blockDim.x + threadIdx.x;
    if (i < E) atomicAdd(&g_deg[dst[i]], 1);
}

__global__ void k_dsqrt(int n) {
    int i = blockIdx.x * blockDim.x + threadIdx.x;
    if (i < n) {
        int d = g_deg[i];
        if (d < 1) d = 1;
        g_dsqrt[i] = rsqrtf((float)d);
    }
}

__global__ void k_prep(const float* __restrict__ x0, int n16) {
    int i = blockIdx.x * blockDim.x + threadIdx.x;
    if (i >= n16) return;
    int node = i >> 4;
    int q = i & 15;
    float ds = g_dsqrt[node];
    float4 v = reinterpret_cast<const float4*>(x0)[i];
    reinterpret_cast<float4*>(g_Xt + (size_t)node * OUTF)[q] = v;
    reinterpret_cast<float4*>(g_xs)[i] = make_float4(v.x * ds, v.y * ds, v.z * ds, v.w * ds);
    reinterpret_cast<float4*>(g_agg)[i] = make_float4(0.f, 0.f, 0.f, 0.f);
}

__global__ void k_scatter(const int* __restrict__ src, const int* __restrict__ dst, int E) {
    int lane = threadIdx.x & 31;
    int gw = (blockIdx.x * blockDim.x + threadIdx.x) >> 5;
    int nwarps = (gridDim.x * blockDim.x) >> 5;
    int half = lane >> 4;
    int q = lane & 15;
    for (int e = gw * 2 + half; e < E; e += nwarps * 2) {
        int s = src[e];
        int d = dst[e];
        float4 v = reinterpret_cast<const float4*>(g_xs + (size_t)s * F)[q];
        float* p = g_agg + (size_t)d * F + q * 4;
        asm volatile("red.global.add.v4.f32 [%0], {%1,%2,%3,%4};"
                     :: "l"(p), "f"(v.x), "f"(v.y), "f"(v.z), "f"(v.w) : "memory");
    }
}

template <int STEP>
__global__ void k_combine(const float* __restrict__ x0, const float* __restrict__ lam, int n16) {
    int i = blockIdx.x * blockDim.x + threadIdx.x;
    if (i >= n16) return;
    int node = i >> 4;
    int q = i & 15;
    float ds = g_dsqrt[node];
    float re = 2.0f / lam[0];
    float4 ag = reinterpret_cast<const float4*>(g_agg)[i];
    float4 out;
    if (STEP == 1) {
        float4 c = reinterpret_cast<const float4*>(x0)[i];
        float ca = -re, cc = re - 1.0f;
        out.x = ca * (ag.x * ds) + cc * c.x;
        out.y = ca * (ag.y * ds) + cc * c.y;
        out.z = ca * (ag.z * ds) + cc * c.z;
        out.w = ca * (ag.w * ds) + cc * c.w;
    } else {
        float4 c = reinterpret_cast<const float4*>(g_Xt + (size_t)node * OUTF + (STEP - 1) * F)[q];
        float4 p = reinterpret_cast<const float4*>(g_Xt + (size_t)node * OUTF + (STEP - 2) * F)[q];
        float ca = -2.0f * re, cc = 2.0f * (re - 1.0f);
        out.x = ca * (ag.x * ds) + cc * c.x - p.x;
        out.y = ca * (ag.y * ds) + cc * c.y - p.y;
        out.z = ca * (ag.z * ds) + cc * c.z - p.z;
        out.w = ca * (ag.w * ds) + cc * c.w - p.w;
    }
    reinterpret_cast<float4*>(g_Xt + (size_t)node * OUTF + STEP * F)[q] = out;
    if (STEP < 3) {
        reinterpret_cast<float4*>(g_xs)[i] =
            make_float4(out.x * ds, out.y * ds, out.z * ds, out.w * ds);
        reinterpret_cast<float4*>(g_agg)[i] = make_float4(0.f, 0.f, 0.f, 0.f);
    }
}

// ================= tf32 mma.sync GEMM: out = relu(Xt @ W + b) =================

__device__ __forceinline__ uint32_t f2tf32(float f) {
    uint32_t o;
    asm("cvt.rna.tf32.f32 %0, %1;" : "=r"(o) : "f"(f));
    return o;
}

// W [K,N] fp32 -> g_Wt [K,N] tf32 bits (one-time per launch, ~2us)
__global__ void k_wt(const float* __restrict__ Wm) {
    int i = blockIdx.x * blockDim.x + threadIdx.x;   // 0..65535
    g_Wt[i] = f2tf32(Wm[i]);
}

#define BM 128
#define BN 128
#define BK 16
#define LDA (BM + 4)   // 132
#define LDB (BN + 4)   // 132

__device__ __forceinline__ void mma_tf32(float* c, const uint32_t* a, const uint32_t* b) {
    asm volatile(
        "mma.sync.aligned.m16n8k8.row.col.f32.tf32.tf32.f32 "
        "{%0,%1,%2,%3}, {%4,%5,%6,%7}, {%8,%9}, {%0,%1,%2,%3};"
        : "+f"(c[0]), "+f"(c[1]), "+f"(c[2]), "+f"(c[3])
        : "r"(a[0]), "r"(a[1]), "r"(a[2]), "r"(a[3]), "r"(b[0]), "r"(b[1]));
}

// Load one BMxBK A tile (cvt fp32->tf32, store COL-major As[k][m]) and one
// BKxBN B tile (tf32 bits, row-major Bs[k][n]).
__device__ __forceinline__ void g2s(uint32_t (*As)[LDA], uint32_t (*Bs)[LDB],
                                    int bm, int bn, int k0, int M, int tid) {
    // A: 128 rows x 16 k, 256 threads -> each thread 8 elems (2 float4 along k)
    int m = tid >> 1;
    int ac = (tid & 1) * 8;
    float4 v0, v1;
    if (bm + m < M) {
        const float* p = g_Xt + (size_t)(bm + m) * OUTF + k0 + ac;
        v0 = *reinterpret_cast<const float4*>(p);
        v1 = *reinterpret_cast<const float4*>(p + 4);
    } else {
        v0 = make_float4(0.f, 0.f, 0.f, 0.f);
        v1 = v0;
    }
    As[ac + 0][m] = f2tf32(v0.x);
    As[ac + 1][m] = f2tf32(v0.y);
    As[ac + 2][m] = f2tf32(v0.z);
    As[ac + 3][m] = f2tf32(v0.w);
    As[ac + 4][m] = f2tf32(v1.x);
    As[ac + 5][m] = f2tf32(v1.y);
    As[ac + 6][m] = f2tf32(v1.z);
    As[ac + 7][m] = f2tf32(v1.w);
    // B: 16 k x 128 n
    int br = tid >> 4;
    int bc = (tid & 15) * 8;
    const uint32_t* q = g_Wt + (k0 + br) * OUTF + bn + bc;
    uint4 w0 = *reinterpret_cast<const uint4*>(q);
    uint4 w1 = *reinterpret_cast<const uint4*>(q + 4);
    *reinterpret_cast<uint4*>(&Bs[br][bc]) = w0;
    *reinterpret_cast<uint4*>(&Bs[br][bc + 4]) = w1;
}

__global__ __launch_bounds__(256, 2)
void k_gemm_mma(const float* __restrict__ bias, float* __restrict__ out, int M) {
    __shared__ uint32_t As[2][BK][LDA];
    __shared__ uint32_t Bs[2][BK][LDB];

    int tid = threadIdx.x;
    int lane = tid & 31;
    int wid = tid >> 5;
    int wm = wid & 1;        // 2 warps in M
    int wn = wid >> 1;       // 4 warps in N
    int g = lane >> 2;       // groupID
    int ti = lane & 3;       // thread-in-group
    int bm = blockIdx.x * BM;
    int bn = blockIdx.y * BN;

    float acc[4][4][4];
#pragma unroll
    for (int mf = 0; mf < 4; mf++)
#pragma unroll
        for (int nf = 0; nf < 4; nf++)
#pragma unroll
            for (int r = 0; r < 4; r++) acc[mf][nf][r] = 0.f;

    g2s(As[0], Bs[0], bm, bn, 0, M, tid);
    __syncthreads();

#pragma unroll 1
    for (int t = 0; t < OUTF / BK; t++) {
        int cur = t & 1;
        if (t < OUTF / BK - 1)
            g2s(As[cur ^ 1], Bs[cur ^ 1], bm, bn, (t + 1) * BK, M, tid);

#pragma unroll
        for (int ks = 0; ks < 2; ks++) {
            int kb = ks * 8;
            uint32_t af[4][4], bf[4][2];
#pragma unroll
            for (int mf = 0; mf < 4; mf++) {
                int m = wm * 64 + mf * 16 + g;
                af[mf][0] = As[cur][kb + ti][m];
                af[mf][1] = As[cur][kb + ti][m + 8];
                af[mf][2] = As[cur][kb + ti + 4][m];
                af[mf][3] = As[cur][kb + ti + 4][m + 8];
            }
#pragma unroll
            for (int nf = 0; nf < 4; nf++) {
                int n = wn * 32 + nf * 8 + g;
                bf[nf][0] = Bs[cur][kb + ti][n];
                bf[nf][1] = Bs[cur][kb + ti + 4][n];
            }
#pragma unroll
            for (int mf = 0; mf < 4; mf++)
#pragma unroll
                for (int nf = 0; nf < 4; nf++)
                    mma_tf32(acc[mf][nf], af[mf], bf[nf]);
        }
        __syncthreads();
    }

    // epilogue: bias + relu, float2 stores
#pragma unroll
    for (int mf = 0; mf < 4; mf++) {
        int row0 = bm + wm * 64 + mf * 16 + g;
#pragma unroll
        for (int nf = 0; nf < 4; nf++) {
            int col = bn + wn * 32 + nf * 8 + ti * 2;
            float2 bb = *reinterpret_cast<const float2*>(bias + col);
            if (row0 < M) {
                float2 o;
                o.x = fmaxf(acc[mf][nf][0] + bb.x, 0.f);
                o.y = fmaxf(acc[mf][nf][1] + bb.y, 0.f);
                *reinterpret_cast<float2*>(out + (size_t)row0 * OUTF + col) = o;
            }
            if (row0 + 8 < M) {
                float2 o;
                o.x = fmaxf(acc[mf][nf][2] + bb.x, 0.f);
                o.y = fmaxf(acc[mf][nf][3] + bb.y, 0.f);
                *reinterpret_cast<float2*>(out + (size_t)(row0 + 8) * OUTF + col) = o;
            }
        }
    }
}

// ================= launch =================

extern "C" void kernel_launch(void* const* d_in, const int* in_sizes, int n_in,
                              void* d_out, int out_size) {
    const float* signal = (const float*)d_in[0];
    const int*   src    = (const int*)d_in[1];
    const int*   dst    = (const int*)d_in[2];
    const float* lam    = (const float*)d_in[3];
    const float* Wm     = (const float*)d_in[4];
    const float* bias   = (const float*)d_in[5];
    float*       out    = (float*)d_out;

    int N = in_sizes[0] / F;
    int E = in_sizes[1];
    int n16 = N * F4;

    k_zero_deg<<<(N + 255) / 256, 256>>>(N);
    k_hist<<<(E + 255) / 256, 256>>>(dst, E);
    k_dsqrt<<<(N + 255) / 256, 256>>>(N);
    k_prep<<<(n16 + 255) / 256, 256>>>(signal, n16);
    k_wt<<<OUTF * OUTF / 256, 256>>>(Wm);

    k_scatter<<<2048, 256>>>(src, dst, E);
    k_combine<1><<<(n16 + 255) / 256, 256>>>(signal, lam, n16);
    k_scatter<<<2048, 256>>>(src, dst, E);
    k_combine<2><<<(n16 + 255) / 256, 256>>>(signal, lam, n16);
    k_scatter<<<2048, 256>>>(src, dst, E);
    k_combine<3><<<(n16 + 255) / 256, 256>>>(signal, lam, n16);

    dim3 gg((N + BM - 1) / BM, OUTF / BN);
    k_gemm_mma<<<gg, 256>>>(bias, out, N);
}

// round 8
// speedup vs baseline: 1.8080x; 1.3867x over previous
#include <cuda_runtime.h>
#include <cstdint>

#define NN      50000
#define NE      800000
#define F       64
#define F4      16
#define OUTF    256
#define SCAN_B  512
#define NBLK    ((NN + SCAN_B - 1) / SCAN_B)   // 98

// -------- scratch (device globals; no allocation allowed) --------
__device__ float g_dsqrt[NN];
__device__ int   g_deg[NN];
__device__ int   g_rowptr[NN + 1];
__device__ int   g_cur[NN];
__device__ int   g_bsum[NBLK];
__device__ int   g_csrc[NE];
__device__ float g_xs[NN * F];                   // ping
__device__ float g_xs2[NN * F];                  // pong
__device__ float g_Xt[(size_t)NN * OUTF];        // [N, 256] = concat(X0..X3)
__device__ uint32_t g_Wt[OUTF * OUTF];           // W [K,N] tf32 bits

// ================= degree / normalization =================

__global__ void k_zero_deg(int n) {
    int i = blockIdx.x * blockDim.x + threadIdx.x;
    if (i < n) g_deg[i] = 0;
}

__global__ void k_hist(const int* __restrict__ dst, int E) {
    int i = blockIdx.x * blockDim.x + threadIdx.x;
    if (i < E) atomicAdd(&g_deg[dst[i]], 1);
}

__global__ void k_dsqrt(int n) {
    int i = blockIdx.x * blockDim.x + threadIdx.x;
    if (i < n) {
        int d = g_deg[i];
        if (d < 1) d = 1;
        g_dsqrt[i] = rsqrtf((float)d);
    }
}

// ================= CSR build =================

__global__ void k_scan1(int n) {
    __shared__ int sh[SCAN_B];
    int t = threadIdx.x;
    int i = blockIdx.x * SCAN_B + t;
    int v = (i < n) ? g_deg[i] : 0;
    sh[t] = v;
    __syncthreads();
#pragma unroll
    for (int off = 1; off < SCAN_B; off <<= 1) {
        int x = (t >= off) ? sh[t - off] : 0;
        __syncthreads();
        sh[t] += x;
        __syncthreads();
    }
    int incl = sh[t];
    if (i < n) g_rowptr[i] = incl - v;   // block-local exclusive
    if (t == SCAN_B - 1) g_bsum[blockIdx.x] = incl;
}

__global__ void k_scan2() {
    __shared__ int sh[128];
    int t = threadIdx.x;
    int v = (t < NBLK) ? g_bsum[t] : 0;
    sh[t] = v;
    __syncthreads();
#pragma unroll
    for (int off = 1; off < 128; off <<= 1) {
        int x = (t >= off) ? sh[t - off] : 0;
        __syncthreads();
        sh[t] += x;
        __syncthreads();
    }
    if (t < NBLK) g_bsum[t] = sh[t] - v;  // exclusive
}

__global__ void k_scan3(int n, int E) {
    int i = blockIdx.x * blockDim.x + threadIdx.x;
    if (i < n) {
        int r = g_rowptr[i] + g_bsum[i / SCAN_B];
        g_rowptr[i] = r;
        g_cur[i] = r;
    }
    if (i == 0) g_rowptr[n] = E;
}

__global__ void k_fill(const int* __restrict__ src, const int* __restrict__ dst, int E) {
    int i = blockIdx.x * blockDim.x + threadIdx.x;
    if (i < E) {
        int pos = atomicAdd(&g_cur[dst[i]], 1);
        g_csrc[pos] = src[i];
    }
}

// ================= prep: Xt[:,0:64]=X0, xs = X0*dsqrt =================

__global__ void k_prep(const float* __restrict__ x0, int n16) {
    int i = blockIdx.x * blockDim.x + threadIdx.x;
    if (i >= n16) return;
    int node = i >> 4;
    int q = i & 15;
    float ds = g_dsqrt[node];
    float4 v = reinterpret_cast<const float4*>(x0)[i];
    reinterpret_cast<float4*>(g_Xt + (size_t)node * OUTF)[q] = v;
    reinterpret_cast<float4*>(g_xs)[i] = make_float4(v.x * ds, v.y * ds, v.z * ds, v.w * ds);
}

// ================= fused SpMV + Chebyshev combine (ping-pong xs) ============
// Half-warp per node: 16 lanes cover the 64-float row as float4[16].
// agg = sum_{e in csr[node]} xin[src_e];  L = agg * ds
// STEP==1: out = -re*L + (re-1)*X0
// STEP>=2: out = -2re*L + 2(re-1)*X_{s-1} - X_{s-2}
// Reads xin only; writes xout only (different buffer) -> no cross-block race.
template <int STEP>
__global__ void k_spmv(const float* __restrict__ xin, float* __restrict__ xout,
                       const float* __restrict__ x0, const float* __restrict__ lam, int N) {
    int lane = threadIdx.x & 31;
    int gw = (blockIdx.x * blockDim.x + threadIdx.x) >> 5;
    int node = gw * 2 + (lane >> 4);
    int q = lane & 15;
    if (node >= N) return;

    int beg = g_rowptr[node];
    int end = g_rowptr[node + 1];
    float4 acc = make_float4(0.f, 0.f, 0.f, 0.f);
    int e = beg;
    for (; e + 2 <= end; e += 2) {
        int s0 = g_csrc[e];
        int s1 = g_csrc[e + 1];
        float4 v0 = reinterpret_cast<const float4*>(xin + (size_t)s0 * F)[q];
        float4 v1 = reinterpret_cast<const float4*>(xin + (size_t)s1 * F)[q];
        acc.x += v0.x + v1.x;
        acc.y += v0.y + v1.y;
        acc.z += v0.z + v1.z;
        acc.w += v0.w + v1.w;
    }
    if (e < end) {
        int s = g_csrc[e];
        float4 v = reinterpret_cast<const float4*>(xin + (size_t)s * F)[q];
        acc.x += v.x; acc.y += v.y; acc.z += v.z; acc.w += v.w;
    }

    float ds = g_dsqrt[node];
    float re = 2.0f / lam[0];
    float4 out;
    if (STEP == 1) {
        float4 c = reinterpret_cast<const float4*>(x0 + (size_t)node * F)[q];
        float ca = -re, cc = re - 1.0f;
        out.x = ca * (acc.x * ds) + cc * c.x;
        out.y = ca * (acc.y * ds) + cc * c.y;
        out.z = ca * (acc.z * ds) + cc * c.z;
        out.w = ca * (acc.w * ds) + cc * c.w;
    } else {
        float4 c = reinterpret_cast<const float4*>(g_Xt + (size_t)node * OUTF + (STEP - 1) * F)[q];
        float4 p = reinterpret_cast<const float4*>(g_Xt + (size_t)node * OUTF + (STEP - 2) * F)[q];
        float ca = -2.0f * re, cc = 2.0f * (re - 1.0f);
        out.x = ca * (acc.x * ds) + cc * c.x - p.x;
        out.y = ca * (acc.y * ds) + cc * c.y - p.y;
        out.z = ca * (acc.z * ds) + cc * c.z - p.z;
        out.w = ca * (acc.w * ds) + cc * c.w - p.w;
    }
    reinterpret_cast<float4*>(g_Xt + (size_t)node * OUTF + STEP * F)[q] = out;
    if (STEP < 3) {
        reinterpret_cast<float4*>(xout + (size_t)node * F)[q] =
            make_float4(out.x * ds, out.y * ds, out.z * ds, out.w * ds);
    }
}

// ================= tf32 mma.sync GEMM: out = relu(Xt @ W + b) =================

__device__ __forceinline__ uint32_t f2tf32(float f) {
    uint32_t o;
    asm("cvt.rna.tf32.f32 %0, %1;" : "=r"(o) : "f"(f));
    return o;
}

__global__ void k_wt(const float* __restrict__ Wm) {
    int i = blockIdx.x * blockDim.x + threadIdx.x;
    g_Wt[i] = f2tf32(Wm[i]);
}

#define BM 128
#define BN 128
#define BK 16
#define LDA (BM + 4)
#define LDB (BN + 4)

__device__ __forceinline__ void mma_tf32(float* c, const uint32_t* a, const uint32_t* b) {
    asm volatile(
        "mma.sync.aligned.m16n8k8.row.col.f32.tf32.tf32.f32 "
        "{%0,%1,%2,%3}, {%4,%5,%6,%7}, {%8,%9}, {%0,%1,%2,%3};"
        : "+f"(c[0]), "+f"(c[1]), "+f"(c[2]), "+f"(c[3])
        : "r"(a[0]), "r"(a[1]), "r"(a[2]), "r"(a[3]), "r"(b[0]), "r"(b[1]));
}

__device__ __forceinline__ void g2s(uint32_t (*As)[LDA], uint32_t (*Bs)[LDB],
                                    int bm, int bn, int k0, int M, int tid) {
    int m = tid >> 1;
    int ac = (tid & 1) * 8;
    float4 v0, v1;
    if (bm + m < M) {
        const float* p = g_Xt + (size_t)(bm + m) * OUTF + k0 + ac;
        v0 = *reinterpret_cast<const float4*>(p);
        v1 = *reinterpret_cast<const float4*>(p + 4);
    } else {
        v0 = make_float4(0.f, 0.f, 0.f, 0.f);
        v1 = v0;
    }
    As[ac + 0][m] = f2tf32(v0.x);
    As[ac + 1][m] = f2tf32(v0.y);
    As[ac + 2][m] = f2tf32(v0.z);
    As[ac + 3][m] = f2tf32(v0.w);
    As[ac + 4][m] = f2tf32(v1.x);
    As[ac + 5][m] = f2tf32(v1.y);
    As[ac + 6][m] = f2tf32(v1.z);
    As[ac + 7][m] = f2tf32(v1.w);
    int br = tid >> 4;
    int bc = (tid & 15) * 8;
    const uint32_t* qp = g_Wt + (k0 + br) * OUTF + bn + bc;
    uint4 w0 = *reinterpret_cast<const uint4*>(qp);
    uint4 w1 = *reinterpret_cast<const uint4*>(qp + 4);
    *reinterpret_cast<uint4*>(&Bs[br][bc]) = w0;
    *reinterpret_cast<uint4*>(&Bs[br][bc + 4]) = w1;
}

__global__ __launch_bounds__(256, 2)
void k_gemm_mma(const float* __restrict__ bias, float* __restrict__ out, int M) {
    __shared__ uint32_t As[2][BK][LDA];
    __shared__ uint32_t Bs[2][BK][LDB];

    int tid = threadIdx.x;
    int lane = tid & 31;
    int wid = tid >> 5;
    int wm = wid & 1;
    int wn = wid >> 1;
    int g = lane >> 2;
    int ti = lane & 3;
    int bm = blockIdx.x * BM;
    int bn = blockIdx.y * BN;

    float acc[4][4][4];
#pragma unroll
    for (int mf = 0; mf < 4; mf++)
#pragma unroll
        for (int nf = 0; nf < 4; nf++)
#pragma unroll
            for (int r = 0; r < 4; r++) acc[mf][nf][r] = 0.f;

    g2s(As[0], Bs[0], bm, bn, 0, M, tid);
    __syncthreads();

#pragma unroll 1
    for (int t = 0; t < OUTF / BK; t++) {
        int cur = t & 1;
        if (t < OUTF / BK - 1)
            g2s(As[cur ^ 1], Bs[cur ^ 1], bm, bn, (t + 1) * BK, M, tid);

#pragma unroll
        for (int ks = 0; ks < 2; ks++) {
            int kb = ks * 8;
            uint32_t af[4][4], bf[4][2];
#pragma unroll
            for (int mf = 0; mf < 4; mf++) {
                int m = wm * 64 + mf * 16 + g;
                af[mf][0] = As[cur][kb + ti][m];
                af[mf][1] = As[cur][kb + ti][m + 8];
                af[mf][2] = As[cur][kb + ti + 4][m];
                af[mf][3] = As[cur][kb + ti + 4][m + 8];
            }
#pragma unroll
            for (int nf = 0; nf < 4; nf++) {
                int n = wn * 32 + nf * 8 + g;
                bf[nf][0] = Bs[cur][kb + ti][n];
                bf[nf][1] = Bs[cur][kb + ti + 4][n];
            }
#pragma unroll
            for (int mf = 0; mf < 4; mf++)
#pragma unroll
                for (int nf = 0; nf < 4; nf++)
                    mma_tf32(acc[mf][nf], af[mf], bf[nf]);
        }
        __syncthreads();
    }

#pragma unroll
    for (int mf = 0; mf < 4; mf++) {
        int row0 = bm + wm * 64 + mf * 16 + g;
#pragma unroll
        for (int nf = 0; nf < 4; nf++) {
            int col = bn + wn * 32 + nf * 8 + ti * 2;
            float2 bb = *reinterpret_cast<const float2*>(bias + col);
            if (row0 < M) {
                float2 o;
                o.x = fmaxf(acc[mf][nf][0] + bb.x, 0.f);
                o.y = fmaxf(acc[mf][nf][1] + bb.y, 0.f);
                *reinterpret_cast<float2*>(out + (size_t)row0 * OUTF + col) = o;
            }
            if (row0 + 8 < M) {
                float2 o;
                o.x = fmaxf(acc[mf][nf][2] + bb.x, 0.f);
                o.y = fmaxf(acc[mf][nf][3] + bb.y, 0.f);
                *reinterpret_cast<float2*>(out + (size_t)(row0 + 8) * OUTF + col) = o;
            }
        }
    }
}

// ================= launch =================

extern "C" void kernel_launch(void* const* d_in, const int* in_sizes, int n_in,
                              void* d_out, int out_size) {
    const float* signal = (const float*)d_in[0];
    const int*   src    = (const int*)d_in[1];
    const int*   dst    = (const int*)d_in[2];
    const float* lam    = (const float*)d_in[3];
    const float* Wm     = (const float*)d_in[4];
    const float* bias   = (const float*)d_in[5];
    float*       out    = (float*)d_out;

    int N = in_sizes[0] / F;
    int E = in_sizes[1];
    int n16 = N * F4;

    k_zero_deg<<<(N + 255) / 256, 256>>>(N);
    k_hist<<<(E + 255) / 256, 256>>>(dst, E);
    k_dsqrt<<<(N + 255) / 256, 256>>>(N);

    k_scan1<<<NBLK, SCAN_B>>>(N);
    k_scan2<<<1, 128>>>();
    k_scan3<<<(N + 255) / 256, 256>>>(N, E);
    k_fill<<<(E + 255) / 256, 256>>>(src, dst, E);

    k_prep<<<(n16 + 255) / 256, 256>>>(signal, n16);
    k_wt<<<OUTF * OUTF / 256, 256>>>(Wm);

    // device-global symbol addresses are resolvable from host via cudaGetSymbolAddress,
    // but simpler: pass via kernels that take pointers — use helper launches below.
    float* xs_ping = nullptr;
    float* xs_pong = nullptr;
    cudaGetSymbolAddress((void**)&xs_ping, g_xs);
    cudaGetSymbolAddress((void**)&xs_pong, g_xs2);

    int nb_spmv = (N * 16 + 255) / 256;   // 2 nodes per warp, 8 warps per block
    k_spmv<1><<<nb_spmv, 256>>>(xs_ping, xs_pong, signal, lam, N);
    k_spmv<2><<<nb_spmv, 256>>>(xs_pong, xs_ping, signal, lam, N);
    k_spmv<3><<<nb_spmv, 256>>>(xs_ping, xs_pong, signal, lam, N);

    dim3 gg((N + BM - 1) / BM, OUTF / BN);
    k_gemm_mma<<<gg, 256>>>(bias, out, N);
}

// round 9
// speedup vs baseline: 2.0814x; 1.1512x over previous
#include <cuda_runtime.h>
#include <cstdint>

#define NN      50000
#define NE      800000
#define F       64
#define F4      16
#define OUTF    256
#define SCAN_B  512
#define NBLK    ((NN + SCAN_B - 1) / SCAN_B)   // 98

// -------- scratch (device globals; no allocation allowed) --------
__device__ float g_dsqrt[NN];
__device__ int   g_deg[NN];
__device__ int   g_rowptr[NN + 1];
__device__ int   g_cur[NN];
__device__ int   g_bsum[NBLK];
__device__ int   g_csrc[NE];
__device__ float g_xs[NN * F];                   // ping
__device__ float g_xs2[NN * F];                  // pong
__device__ float g_Xt[(size_t)NN * OUTF];        // fp32 concat (recurrence reads blocks 0..2)
__device__ uint32_t g_Xtt[(size_t)NN * OUTF];    // tf32 bits concat (GEMM A operand)
__device__ uint32_t g_Wt[OUTF * OUTF];           // W [K,N] tf32 bits

// ================= degree / normalization =================

__global__ void k_zero_deg(int n) {
    int i = blockIdx.x * blockDim.x + threadIdx.x;
    if (i < n) g_deg[i] = 0;
}

__global__ void k_hist(const int* __restrict__ dst, int E) {
    int i = blockIdx.x * blockDim.x + threadIdx.x;
    if (i < E) atomicAdd(&g_deg[dst[i]], 1);
}

__global__ void k_dsqrt(int n) {
    int i = blockIdx.x * blockDim.x + threadIdx.x;
    if (i < n) {
        int d = g_deg[i];
        if (d < 1) d = 1;
        g_dsqrt[i] = rsqrtf((float)d);
    }
}

// ================= CSR build =================

__global__ void k_scan1(int n) {
    __shared__ int sh[SCAN_B];
    int t = threadIdx.x;
    int i = blockIdx.x * SCAN_B + t;
    int v = (i < n) ? g_deg[i] : 0;
    sh[t] = v;
    __syncthreads();
#pragma unroll
    for (int off = 1; off < SCAN_B; off <<= 1) {
        int x = (t >= off) ? sh[t - off] : 0;
        __syncthreads();
        sh[t] += x;
        __syncthreads();
    }
    int incl = sh[t];
    if (i < n) g_rowptr[i] = incl - v;
    if (t == SCAN_B - 1) g_bsum[blockIdx.x] = incl;
}

__global__ void k_scan2() {
    __shared__ int sh[128];
    int t = threadIdx.x;
    int v = (t < NBLK) ? g_bsum[t] : 0;
    sh[t] = v;
    __syncthreads();
#pragma unroll
    for (int off = 1; off < 128; off <<= 1) {
        int x = (t >= off) ? sh[t - off] : 0;
        __syncthreads();
        sh[t] += x;
        __syncthreads();
    }
    if (t < NBLK) g_bsum[t] = sh[t] - v;
}

__global__ void k_scan3(int n, int E) {
    int i = blockIdx.x * blockDim.x + threadIdx.x;
    if (i < n) {
        int r = g_rowptr[i] + g_bsum[i / SCAN_B];
        g_rowptr[i] = r;
        g_cur[i] = r;
    }
    if (i == 0) g_rowptr[n] = E;
}

__global__ void k_fill(const int* __restrict__ src, const int* __restrict__ dst, int E) {
    int i = blockIdx.x * blockDim.x + threadIdx.x;
    if (i < E) {
        int pos = atomicAdd(&g_cur[dst[i]], 1);
        g_csrc[pos] = src[i];
    }
}

// ================= tf32 helpers =================

__device__ __forceinline__ uint32_t f2tf32(float f) {
    uint32_t o;
    asm("cvt.rna.tf32.f32 %0, %1;" : "=r"(o) : "f"(f));
    return o;
}

__global__ void k_wt(const float* __restrict__ Wm) {
    int i = blockIdx.x * blockDim.x + threadIdx.x;
    g_Wt[i] = f2tf32(Wm[i]);
}

// ================= prep: Xt/Xtt block0, xs = X0*dsqrt =================

__global__ void k_prep(const float* __restrict__ x0, int n16) {
    int i = blockIdx.x * blockDim.x + threadIdx.x;
    if (i >= n16) return;
    int node = i >> 4;
    int q = i & 15;
    float ds = g_dsqrt[node];
    float4 v = reinterpret_cast<const float4*>(x0)[i];
    reinterpret_cast<float4*>(g_Xt + (size_t)node * OUTF)[q] = v;
    uint4 u;
    u.x = f2tf32(v.x); u.y = f2tf32(v.y); u.z = f2tf32(v.z); u.w = f2tf32(v.w);
    reinterpret_cast<uint4*>(g_Xtt + (size_t)node * OUTF)[q] = u;
    reinterpret_cast<float4*>(g_xs)[i] = make_float4(v.x * ds, v.y * ds, v.z * ds, v.w * ds);
}

// ================= fused SpMV + Chebyshev combine (ping-pong xs) ============

template <int STEP>
__global__ void k_spmv(const float* __restrict__ xin, float* __restrict__ xout,
                       const float* __restrict__ x0, const float* __restrict__ lam, int N) {
    int lane = threadIdx.x & 31;
    int gw = (blockIdx.x * blockDim.x + threadIdx.x) >> 5;
    int node = gw * 2 + (lane >> 4);
    int q = lane & 15;
    if (node >= N) return;

    int beg = g_rowptr[node];
    int end = g_rowptr[node + 1];
    float4 acc = make_float4(0.f, 0.f, 0.f, 0.f);
    int e = beg;
    for (; e + 4 <= end; e += 4) {
        int s0 = g_csrc[e];
        int s1 = g_csrc[e + 1];
        int s2 = g_csrc[e + 2];
        int s3 = g_csrc[e + 3];
        float4 v0 = reinterpret_cast<const float4*>(xin + (size_t)s0 * F)[q];
        float4 v1 = reinterpret_cast<const float4*>(xin + (size_t)s1 * F)[q];
        float4 v2 = reinterpret_cast<const float4*>(xin + (size_t)s2 * F)[q];
        float4 v3 = reinterpret_cast<const float4*>(xin + (size_t)s3 * F)[q];
        acc.x += (v0.x + v1.x) + (v2.x + v3.x);
        acc.y += (v0.y + v1.y) + (v2.y + v3.y);
        acc.z += (v0.z + v1.z) + (v2.z + v3.z);
        acc.w += (v0.w + v1.w) + (v2.w + v3.w);
    }
    for (; e < end; e++) {
        int s = g_csrc[e];
        float4 v = reinterpret_cast<const float4*>(xin + (size_t)s * F)[q];
        acc.x += v.x; acc.y += v.y; acc.z += v.z; acc.w += v.w;
    }

    float ds = g_dsqrt[node];
    float re = 2.0f / lam[0];
    float4 out;
    if (STEP == 1) {
        float4 c = reinterpret_cast<const float4*>(x0 + (size_t)node * F)[q];
        float ca = -re, cc = re - 1.0f;
        out.x = ca * (acc.x * ds) + cc * c.x;
        out.y = ca * (acc.y * ds) + cc * c.y;
        out.z = ca * (acc.z * ds) + cc * c.z;
        out.w = ca * (acc.w * ds) + cc * c.w;
    } else {
        float4 c = reinterpret_cast<const float4*>(g_Xt + (size_t)node * OUTF + (STEP - 1) * F)[q];
        float4 p = reinterpret_cast<const float4*>(g_Xt + (size_t)node * OUTF + (STEP - 2) * F)[q];
        float ca = -2.0f * re, cc = 2.0f * (re - 1.0f);
        out.x = ca * (acc.x * ds) + cc * c.x - p.x;
        out.y = ca * (acc.y * ds) + cc * c.y - p.y;
        out.z = ca * (acc.z * ds) + cc * c.z - p.z;
        out.w = ca * (acc.w * ds) + cc * c.w - p.w;
    }
    // tf32 copy for the GEMM (all steps)
    uint4 u;
    u.x = f2tf32(out.x); u.y = f2tf32(out.y); u.z = f2tf32(out.z); u.w = f2tf32(out.w);
    reinterpret_cast<uint4*>(g_Xtt + (size_t)node * OUTF + STEP * F)[q] = u;
    if (STEP < 3) {
        // fp32 copy only needed by the recurrence (blocks 0..2)
        reinterpret_cast<float4*>(g_Xt + (size_t)node * OUTF + STEP * F)[q] = out;
        reinterpret_cast<float4*>(xout + (size_t)node * F)[q] =
            make_float4(out.x * ds, out.y * ds, out.z * ds, out.w * ds);
    }
}

// ========== cp.async-pipelined tf32 mma GEMM: out = relu(Xtt @ Wt + b) ==========

#define BM 128
#define BN 128
#define BK 16
#define G_LDA 20                       // 16 + 4 pad (floats)
#define G_LDB 132                      // 128 + 4 pad (floats)
#define A_BYTES (BM * G_LDA * 4)       // 10240
#define B_BYTES (BK * G_LDB * 4)       // 8448
#define STG_BYTES (A_BYTES + B_BYTES)  // 18688
#define GSTAGES 3
#define G_SMEM (STG_BYTES * GSTAGES)   // 56064

__device__ __forceinline__ void cp16(uint32_t d, const void* s, int szb) {
    asm volatile("cp.async.cg.shared.global [%0], [%1], 16, %2;"
                 :: "r"(d), "l"(s), "r"(szb));
}

__device__ __forceinline__ void g_stage(uint32_t sb, int slot, int bm, int bn,
                                        int k0, int M, int tid) {
    uint32_t ab = sb + slot * STG_BYTES;
    uint32_t bb = ab + A_BYTES;
#pragma unroll
    for (int t = 0; t < 2; t++) {
        int c = (tid << 1) + t;                 // 0..511
        // A: 128 rows x 16 k -> 4 chunks/row
        int row = c >> 2;
        int kc = (c & 3) << 2;
        int sz = (bm + row < M) ? 16 : 0;
        cp16(ab + row * (G_LDA * 4) + (kc << 2),
             g_Xtt + (size_t)(bm + row) * OUTF + k0 + kc, sz);
        // B: 16 rows x 128 n -> 32 chunks/row
        int kr = c >> 5;
        int col = (c & 31) << 2;
        cp16(bb + kr * (G_LDB * 4) + (col << 2),
             g_Wt + (size_t)(k0 + kr) * OUTF + bn + col, 16);
    }
    asm volatile("cp.async.commit_group;" ::: "memory");
}

__device__ __forceinline__ void mma_tf32(float* c, const uint32_t* a, const uint32_t* b) {
    asm volatile(
        "mma.sync.aligned.m16n8k8.row.col.f32.tf32.tf32.f32 "
        "{%0,%1,%2,%3}, {%4,%5,%6,%7}, {%8,%9}, {%0,%1,%2,%3};"
        : "+f"(c[0]), "+f"(c[1]), "+f"(c[2]), "+f"(c[3])
        : "r"(a[0]), "r"(a[1]), "r"(a[2]), "r"(a[3]), "r"(b[0]), "r"(b[1]));
}

__global__ __launch_bounds__(256, 2)
void k_gemm_cp(const float* __restrict__ bias, float* __restrict__ out, int M) {
    extern __shared__ char smem[];
    uint32_t sb = (uint32_t)__cvta_generic_to_shared(smem);

    int tid = threadIdx.x;
    int lane = tid & 31;
    int wid = tid >> 5;
    int wm = wid & 1;
    int wn = wid >> 1;
    int g = lane >> 2;
    int ti = lane & 3;
    int bm = blockIdx.x * BM;
    int bn = blockIdx.y * BN;

    float acc[4][4][4];
#pragma unroll
    for (int mf = 0; mf < 4; mf++)
#pragma unroll
        for (int nf = 0; nf < 4; nf++)
#pragma unroll
            for (int r = 0; r < 4; r++) acc[mf][nf][r] = 0.f;

    g_stage(sb, 0, bm, bn, 0, M, tid);
    g_stage(sb, 1, bm, bn, BK, M, tid);

    const int NT = OUTF / BK;   // 16
#pragma unroll 1
    for (int t = 0; t < NT; t++) {
        asm volatile("cp.async.wait_group 1;" ::: "memory");
        __syncthreads();
        if (t + 2 < NT)
            g_stage(sb, (t + 2) % GSTAGES, bm, bn, (t + 2) * BK, M, tid);
        else
            asm volatile("cp.async.commit_group;" ::: "memory");

        int slot = t % GSTAGES;
        const uint32_t* Asl = (const uint32_t*)(smem + slot * STG_BYTES);
        const uint32_t* Bsl = (const uint32_t*)(smem + slot * STG_BYTES + A_BYTES);

#pragma unroll
        for (int ks = 0; ks < 2; ks++) {
            int kb = ks * 8;
            uint32_t af[4][4], bf[4][2];
#pragma unroll
            for (int mf = 0; mf < 4; mf++) {
                int m = wm * 64 + mf * 16 + g;
                af[mf][0] = Asl[m * G_LDA + kb + ti];
                af[mf][1] = Asl[(m + 8) * G_LDA + kb + ti];
                af[mf][2] = Asl[m * G_LDA + kb + ti + 4];
                af[mf][3] = Asl[(m + 8) * G_LDA + kb + ti + 4];
            }
#pragma unroll
            for (int nf = 0; nf < 4; nf++) {
                int n = wn * 32 + nf * 8 + g;
                bf[nf][0] = Bsl[(kb + ti) * G_LDB + n];
                bf[nf][1] = Bsl[(kb + ti + 4) * G_LDB + n];
            }
#pragma unroll
            for (int mf = 0; mf < 4; mf++)
#pragma unroll
                for (int nf = 0; nf < 4; nf++)
                    mma_tf32(acc[mf][nf], af[mf], bf[nf]);
        }
    }

#pragma unroll
    for (int mf = 0; mf < 4; mf++) {
        int row0 = bm + wm * 64 + mf * 16 + g;
#pragma unroll
        for (int nf = 0; nf < 4; nf++) {
            int col = bn + wn * 32 + nf * 8 + ti * 2;
            float2 bb = *reinterpret_cast<const float2*>(bias + col);
            if (row0 < M) {
                float2 o;
                o.x = fmaxf(acc[mf][nf][0] + bb.x, 0.f);
                o.y = fmaxf(acc[mf][nf][1] + bb.y, 0.f);
                *reinterpret_cast<float2*>(out + (size_t)row0 * OUTF + col) = o;
            }
            if (row0 + 8 < M) {
                float2 o;
                o.x = fmaxf(acc[mf][nf][2] + bb.x, 0.f);
                o.y = fmaxf(acc[mf][nf][3] + bb.y, 0.f);
                *reinterpret_cast<float2*>(out + (size_t)(row0 + 8) * OUTF + col) = o;
            }
        }
    }
}

// ================= launch =================

extern "C" void kernel_launch(void* const* d_in, const int* in_sizes, int n_in,
                              void* d_out, int out_size) {
    const float* signal = (const float*)d_in[0];
    const int*   src    = (const int*)d_in[1];
    const int*   dst    = (const int*)d_in[2];
    const float* lam    = (const float*)d_in[3];
    const float* Wm     = (const float*)d_in[4];
    const float* bias   = (const float*)d_in[5];
    float*       out    = (float*)d_out;

    int N = in_sizes[0] / F;
    int E = in_sizes[1];
    int n16 = N * F4;

    cudaFuncSetAttribute(k_gemm_cp, cudaFuncAttributeMaxDynamicSharedMemorySize, G_SMEM);

    k_zero_deg<<<(N + 255) / 256, 256>>>(N);
    k_hist<<<(E + 255) / 256, 256>>>(dst, E);
    k_dsqrt<<<(N + 255) / 256, 256>>>(N);

    k_scan1<<<NBLK, SCAN_B>>>(N);
    k_scan2<<<1, 128>>>();
    k_scan3<<<(N + 255) / 256, 256>>>(N, E);
    k_fill<<<(E + 255) / 256, 256>>>(src, dst, E);

    k_prep<<<(n16 + 255) / 256, 256>>>(signal, n16);
    k_wt<<<OUTF * OUTF / 256, 256>>>(Wm);

    float* xs_ping = nullptr;
    float* xs_pong = nullptr;
    cudaGetSymbolAddress((void**)&xs_ping, g_xs);
    cudaGetSymbolAddress((void**)&xs_pong, g_xs2);

    int nb_spmv = (N * 16 + 255) / 256;
    k_spmv<1><<<nb_spmv, 256>>>(xs_ping, xs_pong, signal, lam, N);
    k_spmv<2><<<nb_spmv, 256>>>(xs_pong, xs_ping, signal, lam, N);
    k_spmv<3><<<nb_spmv, 256>>>(xs_ping, xs_pong, signal, lam, N);

    dim3 gg((N + BM - 1) / BM, OUTF / BN);
    k_gemm_cp<<<gg, 256, G_SMEM>>>(bias, out, N);
}

// round 10
// speedup vs baseline: 2.6073x; 1.2527x over previous
#include <cuda_runtime.h>
#include <cuda_fp16.h>
#include <cstdint>

#define NN      50000
#define NE      800000
#define F       64
#define F4      16
#define OUTF    256
#define SCAN_B  512
#define NBLK    ((NN + SCAN_B - 1) / SCAN_B)   // 98

// -------- scratch (device globals; no allocation allowed) --------
__device__ float g_dsqrt[NN];
__device__ int   g_deg[NN];
__device__ int   g_rowptr[NN + 1];
__device__ int   g_cur[NN];
__device__ int   g_bsum[NBLK];
__device__ int   g_csrc[NE];
__device__ float g_xs[NN * F];                   // ping
__device__ float g_xs2[NN * F];                  // pong
__device__ float g_Xt[(size_t)NN * OUTF];        // fp32 concat (recurrence reads blocks 0..2)
__device__ __half g_Xh[(size_t)NN * OUTF];       // fp16 concat (GEMM A operand)
__device__ __half g_Wh[OUTF * OUTF];             // W transposed: g_Wh[n*256+k] = W[k][n], fp16

// ================= degree / normalization =================

__global__ void k_zero_deg(int n) {
    int i = blockIdx.x * blockDim.x + threadIdx.x;
    if (i < n) g_deg[i] = 0;
}

__global__ void k_hist(const int* __restrict__ dst, int E) {
    int i = blockIdx.x * blockDim.x + threadIdx.x;
    if (i < E) atomicAdd(&g_deg[dst[i]], 1);
}

__global__ void k_dsqrt(int n) {
    int i = blockIdx.x * blockDim.x + threadIdx.x;
    if (i < n) {
        int d = g_deg[i];
        if (d < 1) d = 1;
        g_dsqrt[i] = rsqrtf((float)d);
    }
}

// ================= CSR build =================

__global__ void k_scan1(int n) {
    __shared__ int ws[16];
    int t = threadIdx.x;
    int lane = t & 31;
    int w = t >> 5;
    int i = blockIdx.x * SCAN_B + t;
    int v = (i < n) ? g_deg[i] : 0;
    int x = v;
#pragma unroll
    for (int o = 1; o < 32; o <<= 1) {
        int y = __shfl_up_sync(0xFFFFFFFFu, x, o);
        if (lane >= o) x += y;
    }
    if (lane == 31) ws[w] = x;
    __syncthreads();
    if (w == 0) {
        int s = (lane < 16) ? ws[lane] : 0;
#pragma unroll
        for (int o = 1; o < 16; o <<= 1) {
            int y = __shfl_up_sync(0xFFFFFFFFu, s, o);
            if (lane >= o) s += y;
        }
        if (lane < 16) ws[lane] = s;
    }
    __syncthreads();
    int base = (w > 0) ? ws[w - 1] : 0;
    int incl = base + x;
    if (i < n) g_rowptr[i] = incl - v;
    if (t == SCAN_B - 1) g_bsum[blockIdx.x] = incl;
}

__global__ void k_scan2() {
    __shared__ int sh[128];
    int t = threadIdx.x;
    int v = (t < NBLK) ? g_bsum[t] : 0;
    sh[t] = v;
    __syncthreads();
#pragma unroll
    for (int off = 1; off < 128; off <<= 1) {
        int x = (t >= off) ? sh[t - off] : 0;
        __syncthreads();
        sh[t] += x;
        __syncthreads();
    }
    if (t < NBLK) g_bsum[t] = sh[t] - v;
}

__global__ void k_scan3(int n, int E) {
    int i = blockIdx.x * blockDim.x + threadIdx.x;
    if (i < n) {
        int r = g_rowptr[i] + g_bsum[i / SCAN_B];
        g_rowptr[i] = r;
        g_cur[i] = r;
    }
    if (i == 0) g_rowptr[n] = E;
}

__global__ void k_fill(const int* __restrict__ src, const int* __restrict__ dst, int E) {
    int i = blockIdx.x * blockDim.x + threadIdx.x;
    if (i < E) {
        int pos = atomicAdd(&g_cur[dst[i]], 1);
        g_csrc[pos] = src[i];
    }
}

// ================= W -> fp16, transposed to [n][k] =================

__global__ void k_wt(const float* __restrict__ Wm) {
    int n = blockIdx.x;      // 0..255
    int k = threadIdx.x;     // 0..255
    g_Wh[(size_t)n * OUTF + k] = __float2half_rn(Wm[(size_t)k * OUTF + n]);
}

// ================= prep: Xt/Xh block0, xs = X0*dsqrt =================

__device__ __forceinline__ void store_h4(__half* base, int q, float4 v) {
    __half2 h0 = __floats2half2_rn(v.x, v.y);
    __half2 h1 = __floats2half2_rn(v.z, v.w);
    uint2 u;
    u.x = *reinterpret_cast<unsigned*>(&h0);
    u.y = *reinterpret_cast<unsigned*>(&h1);
    reinterpret_cast<uint2*>(base)[q] = u;
}

__global__ void k_prep(const float* __restrict__ x0, int n16) {
    int i = blockIdx.x * blockDim.x + threadIdx.x;
    if (i >= n16) return;
    int node = i >> 4;
    int q = i & 15;
    float ds = g_dsqrt[node];
    float4 v = reinterpret_cast<const float4*>(x0)[i];
    reinterpret_cast<float4*>(g_Xt + (size_t)node * OUTF)[q] = v;
    store_h4(g_Xh + (size_t)node * OUTF, q, v);
    reinterpret_cast<float4*>(g_xs)[i] = make_float4(v.x * ds, v.y * ds, v.z * ds, v.w * ds);
}

// ================= fused SpMV + Chebyshev combine (ping-pong xs) ============

template <int STEP>
__global__ void k_spmv(const float* __restrict__ xin, float* __restrict__ xout,
                       const float* __restrict__ x0, const float* __restrict__ lam, int N) {
    int lane = threadIdx.x & 31;
    int gw = (blockIdx.x * blockDim.x + threadIdx.x) >> 5;
    int node = gw * 2 + (lane >> 4);
    int q = lane & 15;
    if (node >= N) return;

    int beg = g_rowptr[node];
    int end = g_rowptr[node + 1];
    float4 acc = make_float4(0.f, 0.f, 0.f, 0.f);
    int e = beg;
    for (; e + 4 <= end; e += 4) {
        int s0 = g_csrc[e];
        int s1 = g_csrc[e + 1];
        int s2 = g_csrc[e + 2];
        int s3 = g_csrc[e + 3];
        float4 v0 = reinterpret_cast<const float4*>(xin + (size_t)s0 * F)[q];
        float4 v1 = reinterpret_cast<const float4*>(xin + (size_t)s1 * F)[q];
        float4 v2 = reinterpret_cast<const float4*>(xin + (size_t)s2 * F)[q];
        float4 v3 = reinterpret_cast<const float4*>(xin + (size_t)s3 * F)[q];
        acc.x += (v0.x + v1.x) + (v2.x + v3.x);
        acc.y += (v0.y + v1.y) + (v2.y + v3.y);
        acc.z += (v0.z + v1.z) + (v2.z + v3.z);
        acc.w += (v0.w + v1.w) + (v2.w + v3.w);
    }
    for (; e < end; e++) {
        int s = g_csrc[e];
        float4 v = reinterpret_cast<const float4*>(xin + (size_t)s * F)[q];
        acc.x += v.x; acc.y += v.y; acc.z += v.z; acc.w += v.w;
    }

    float ds = g_dsqrt[node];
    float re = 2.0f / lam[0];
    float4 out;
    if (STEP == 1) {
        float4 c = reinterpret_cast<const float4*>(x0 + (size_t)node * F)[q];
        float ca = -re, cc = re - 1.0f;
        out.x = ca * (acc.x * ds) + cc * c.x;
        out.y = ca * (acc.y * ds) + cc * c.y;
        out.z = ca * (acc.z * ds) + cc * c.z;
        out.w = ca * (acc.w * ds) + cc * c.w;
    } else {
        float4 c = reinterpret_cast<const float4*>(g_Xt + (size_t)node * OUTF + (STEP - 1) * F)[q];
        float4 p = reinterpret_cast<const float4*>(g_Xt + (size_t)node * OUTF + (STEP - 2) * F)[q];
        float ca = -2.0f * re, cc = 2.0f * (re - 1.0f);
        out.x = ca * (acc.x * ds) + cc * c.x - p.x;
        out.y = ca * (acc.y * ds) + cc * c.y - p.y;
        out.z = ca * (acc.z * ds) + cc * c.z - p.z;
        out.w = ca * (acc.w * ds) + cc * c.w - p.w;
    }
    store_h4(g_Xh + (size_t)node * OUTF + STEP * F, q, out);
    if (STEP < 3) {
        reinterpret_cast<float4*>(g_Xt + (size_t)node * OUTF + STEP * F)[q] = out;
        reinterpret_cast<float4*>(xout + (size_t)node * F)[q] =
            make_float4(out.x * ds, out.y * ds, out.z * ds, out.w * ds);
    }
}

// ===== cp.async-pipelined fp16 mma GEMM: out = relu(Xh @ Wh^T + b) =====
// fp16 operands (same 10-bit mantissa as tf32), fp32 accumulate, m16n8k16.

#define BM 128
#define BN 128
#define BK2 32
#define LDH 40                          // halfs per smem row (conflict-free: (20g+ti)%32 distinct)
#define A2_BYTES (BM * LDH * 2)         // 10240
#define B2_BYTES (BN * LDH * 2)         // 10240
#define STG2 (A2_BYTES + B2_BYTES)      // 20480
#define GST 3
#define G_SMEM2 (STG2 * GST)            // 61440

__device__ __forceinline__ void cp16(uint32_t d, const void* s, int szb) {
    asm volatile("cp.async.cg.shared.global [%0], [%1], 16, %2;"
                 :: "r"(d), "l"(s), "r"(szb));
}

__device__ __forceinline__ void g_stage2(uint32_t sb, int slot, int bm, int bn,
                                         int k0, int M, int tid) {
    uint32_t ab = sb + slot * STG2;
    uint32_t bb = ab + A2_BYTES;
#pragma unroll
    for (int t = 0; t < 4; t++) {
        int c = tid + t * 256;          // 0..1023
        if (c < 512) {
            int row = c >> 2;
            int part = c & 3;
            int sz = (bm + row < M) ? 16 : 0;
            cp16(ab + row * (LDH * 2) + part * 16,
                 g_Xh + (size_t)(bm + row) * OUTF + k0 + part * 8, sz);
        } else {
            int c2 = c - 512;
            int nr = c2 >> 2;
            int part = c2 & 3;
            cp16(bb + nr * (LDH * 2) + part * 16,
                 g_Wh + (size_t)(bn + nr) * OUTF + k0 + part * 8, 16);
        }
    }
    asm volatile("cp.async.commit_group;" ::: "memory");
}

__device__ __forceinline__ void mma_f16(float* c, const uint32_t* a, const uint32_t* b) {
    asm volatile(
        "mma.sync.aligned.m16n8k16.row.col.f32.f16.f16.f32 "
        "{%0,%1,%2,%3}, {%4,%5,%6,%7}, {%8,%9}, {%0,%1,%2,%3};"
        : "+f"(c[0]), "+f"(c[1]), "+f"(c[2]), "+f"(c[3])
        : "r"(a[0]), "r"(a[1]), "r"(a[2]), "r"(a[3]), "r"(b[0]), "r"(b[1]));
}

__global__ __launch_bounds__(256, 2)
void k_gemm_h(const float* __restrict__ bias, float* __restrict__ out, int M) {
    extern __shared__ char smem[];
    uint32_t sb = (uint32_t)__cvta_generic_to_shared(smem);

    int tid = threadIdx.x;
    int lane = tid & 31;
    int wid = tid >> 5;
    int wm = wid & 1;
    int wn = wid >> 1;
    int g = lane >> 2;
    int ti = lane & 3;
    int bm = blockIdx.x * BM;
    int bn = blockIdx.y * BN;

    float acc[4][4][4];
#pragma unroll
    for (int mf = 0; mf < 4; mf++)
#pragma unroll
        for (int nf = 0; nf < 4; nf++)
#pragma unroll
            for (int r = 0; r < 4; r++) acc[mf][nf][r] = 0.f;

    g_stage2(sb, 0, bm, bn, 0, M, tid);
    g_stage2(sb, 1, bm, bn, BK2, M, tid);

    const int NT = OUTF / BK2;   // 8
#pragma unroll 1
    for (int t = 0; t < NT; t++) {
        asm volatile("cp.async.wait_group 1;" ::: "memory");
        __syncthreads();
        if (t + 2 < NT)
            g_stage2(sb, (t + 2) % GST, bm, bn, (t + 2) * BK2, M, tid);
        else
            asm volatile("cp.async.commit_group;" ::: "memory");

        int slot = t % GST;
        const __half* Asl = reinterpret_cast<const __half*>(smem + slot * STG2);
        const __half* Bsl = reinterpret_cast<const __half*>(smem + slot * STG2 + A2_BYTES);

#pragma unroll
        for (int ks = 0; ks < 2; ks++) {
            int ko = ks * 16;
            uint32_t af[4][4], bf[4][2];
#pragma unroll
            for (int mf = 0; mf < 4; mf++) {
                int m = wm * 64 + mf * 16 + g;
                af[mf][0] = *reinterpret_cast<const uint32_t*>(Asl + m * LDH + ko + 2 * ti);
                af[mf][1] = *reinterpret_cast<const uint32_t*>(Asl + (m + 8) * LDH + ko + 2 * ti);
                af[mf][2] = *reinterpret_cast<const uint32_t*>(Asl + m * LDH + ko + 2 * ti + 8);
                af[mf][3] = *reinterpret_cast<const uint32_t*>(Asl + (m + 8) * LDH + ko + 2 * ti + 8);
            }
#pragma unroll
            for (int nf = 0; nf < 4; nf++) {
                int n = wn * 32 + nf * 8 + g;
                bf[nf][0] = *reinterpret_cast<const uint32_t*>(Bsl + n * LDH + ko + 2 * ti);
                bf[nf][1] = *reinterpret_cast<const uint32_t*>(Bsl + n * LDH + ko + 2 * ti + 8);
            }
#pragma unroll
            for (int mf = 0; mf < 4; mf++)
#pragma unroll
                for (int nf = 0; nf < 4; nf++)
                    mma_f16(acc[mf][nf], af[mf], bf[nf]);
        }
    }

#pragma unroll
    for (int mf = 0; mf < 4; mf++) {
        int row0 = bm + wm * 64 + mf * 16 + g;
#pragma unroll
        for (int nf = 0; nf < 4; nf++) {
            int col = bn + wn * 32 + nf * 8 + ti * 2;
            float2 bb = *reinterpret_cast<const float2*>(bias + col);
            if (row0 < M) {
                float2 o;
                o.x = fmaxf(acc[mf][nf][0] + bb.x, 0.f);
                o.y = fmaxf(acc[mf][nf][1] + bb.y, 0.f);
                *reinterpret_cast<float2*>(out + (size_t)row0 * OUTF + col) = o;
            }
            if (row0 + 8 < M) {
                float2 o;
                o.x = fmaxf(acc[mf][nf][2] + bb.x, 0.f);
                o.y = fmaxf(acc[mf][nf][3] + bb.y, 0.f);
                *reinterpret_cast<float2*>(out + (size_t)(row0 + 8) * OUTF + col) = o;
            }
        }
    }
}

// ================= launch =================

extern "C" void kernel_launch(void* const* d_in, const int* in_sizes, int n_in,
                              void* d_out, int out_size) {
    const float* signal = (const float*)d_in[0];
    const int*   src    = (const int*)d_in[1];
    const int*   dst    = (const int*)d_in[2];
    const float* lam    = (const float*)d_in[3];
    const float* Wm     = (const float*)d_in[4];
    const float* bias   = (const float*)d_in[5];
    float*       out    = (float*)d_out;

    int N = in_sizes[0] / F;
    int E = in_sizes[1];
    int n16 = N * F4;

    cudaFuncSetAttribute(k_gemm_h, cudaFuncAttributeMaxDynamicSharedMemorySize, G_SMEM2);

    k_zero_deg<<<(N + 255) / 256, 256>>>(N);
    k_hist<<<(E + 255) / 256, 256>>>(dst, E);
    k_dsqrt<<<(N + 255) / 256, 256>>>(N);

    k_scan1<<<NBLK, SCAN_B>>>(N);
    k_scan2<<<1, 128>>>();
    k_scan3<<<(N + 255) / 256, 256>>>(N, E);
    k_fill<<<(E + 255) / 256, 256>>>(src, dst, E);

    k_prep<<<(n16 + 255) / 256, 256>>>(signal, n16);
    k_wt<<<OUTF, OUTF>>>(Wm);

    float* xs_ping = nullptr;
    float* xs_pong = nullptr;
    cudaGetSymbolAddress((void**)&xs_ping, g_xs);
    cudaGetSymbolAddress((void**)&xs_pong, g_xs2);

    int nb_spmv = (N * 16 + 255) / 256;
    k_spmv<1><<<nb_spmv, 256>>>(xs_ping, xs_pong, signal, lam, N);
    k_spmv<2><<<nb_spmv, 256>>>(xs_pong, xs_ping, signal, lam, N);
    k_spmv<3><<<nb_spmv, 256>>>(xs_ping, xs_pong, signal, lam, N);

    dim3 gg((N + BM - 1) / BM, OUTF / BN);
    k_gemm_h<<<gg, 256, G_SMEM2>>>(bias, out, N);
}

// round 11
// speedup vs baseline: 2.8257x; 1.0838x over previous
#include <cuda_runtime.h>
#include <cuda_fp16.h>
#include <cstdint>

#define NN      50000
#define NE      800000
#define F       64
#define F4      16
#define OUTF    256
#define SCAN_B  512
#define NBLK    ((NN + SCAN_B - 1) / SCAN_B)   // 98

// -------- scratch (device globals; no allocation allowed) --------
__device__ float g_dsqrt[NN];
__device__ int   g_deg[NN];
__device__ int   g_rowptr[NN + 1];
__device__ int   g_cur[NN];
__device__ int   g_bsum[NBLK];
__device__ int   g_csrc[NE];
__device__ __half g_hxs[NN * F];                 // ping (fp16 normalized features)
__device__ __half g_hxs2[NN * F];                // pong
__device__ float g_Xt[(size_t)NN * OUTF];        // fp32 concat (recurrence reads blocks 0..2)
__device__ __half g_Xh[(size_t)NN * OUTF];       // fp16 concat (GEMM A operand)
__device__ __half g_Wh[OUTF * OUTF];             // W transposed: g_Wh[n*256+k] = W[k][n], fp16

// ================= degree =================

__global__ void k_zero_deg(int n) {
    int i = blockIdx.x * blockDim.x + threadIdx.x;
    if (i < n) g_deg[i] = 0;
}

__global__ void k_hist(const int* __restrict__ dst, int E) {
    int i = blockIdx.x * blockDim.x + threadIdx.x;
    if (i < E) atomicAdd(&g_deg[dst[i]], 1);
}

// ================= CSR build (+ dsqrt fused into scan3) =================

__global__ void k_scan1(int n) {
    __shared__ int ws[16];
    int t = threadIdx.x;
    int lane = t & 31;
    int w = t >> 5;
    int i = blockIdx.x * SCAN_B + t;
    int v = (i < n) ? g_deg[i] : 0;
    int x = v;
#pragma unroll
    for (int o = 1; o < 32; o <<= 1) {
        int y = __shfl_up_sync(0xFFFFFFFFu, x, o);
        if (lane >= o) x += y;
    }
    if (lane == 31) ws[w] = x;
    __syncthreads();
    if (w == 0) {
        int s = (lane < 16) ? ws[lane] : 0;
#pragma unroll
        for (int o = 1; o < 16; o <<= 1) {
            int y = __shfl_up_sync(0xFFFFFFFFu, s, o);
            if (lane >= o) s += y;
        }
        if (lane < 16) ws[lane] = s;
    }
    __syncthreads();
    int base = (w > 0) ? ws[w - 1] : 0;
    int incl = base + x;
    if (i < n) g_rowptr[i] = incl - v;
    if (t == SCAN_B - 1) g_bsum[blockIdx.x] = incl;
}

__global__ void k_scan2() {
    __shared__ int sh[128];
    int t = threadIdx.x;
    int v = (t < NBLK) ? g_bsum[t] : 0;
    sh[t] = v;
    __syncthreads();
#pragma unroll
    for (int off = 1; off < 128; off <<= 1) {
        int x = (t >= off) ? sh[t - off] : 0;
        __syncthreads();
        sh[t] += x;
        __syncthreads();
    }
    if (t < NBLK) g_bsum[t] = sh[t] - v;
}

__global__ void k_scan3(int n, int E) {
    int i = blockIdx.x * blockDim.x + threadIdx.x;
    if (i < n) {
        int r = g_rowptr[i] + g_bsum[i / SCAN_B];
        g_rowptr[i] = r;
        g_cur[i] = r;
        int d = g_deg[i];
        if (d < 1) d = 1;
        g_dsqrt[i] = rsqrtf((float)d);
    }
    if (i == 0) g_rowptr[n] = E;
}

__global__ void k_fill(const int* __restrict__ src, const int* __restrict__ dst, int E) {
    int i = blockIdx.x * blockDim.x + threadIdx.x;
    if (i < E) {
        int pos = atomicAdd(&g_cur[dst[i]], 1);
        g_csrc[pos] = src[i];
    }
}

// ================= W -> fp16, transposed to [n][k] =================

__global__ void k_wt(const float* __restrict__ Wm) {
    int n = blockIdx.x;
    int k = threadIdx.x;
    g_Wh[(size_t)n * OUTF + k] = __float2half_rn(Wm[(size_t)k * OUTF + n]);
}

// ================= fp16 pack helpers =================

__device__ __forceinline__ uint2 pack_h4(float4 v) {
    __half2 h0 = __floats2half2_rn(v.x, v.y);
    __half2 h1 = __floats2half2_rn(v.z, v.w);
    uint2 u;
    u.x = *reinterpret_cast<unsigned*>(&h0);
    u.y = *reinterpret_cast<unsigned*>(&h1);
    return u;
}

// ================= prep: Xt/Xh block0, hxs = fp16(X0*dsqrt) =================

__global__ void k_prep(const float* __restrict__ x0, int n16) {
    int i = blockIdx.x * blockDim.x + threadIdx.x;
    if (i >= n16) return;
    int node = i >> 4;
    int q = i & 15;
    float ds = g_dsqrt[node];
    float4 v = reinterpret_cast<const float4*>(x0)[i];
    reinterpret_cast<float4*>(g_Xt + (size_t)node * OUTF)[q] = v;
    reinterpret_cast<uint2*>(g_Xh + (size_t)node * OUTF)[q] = pack_h4(v);
    reinterpret_cast<uint2*>(g_hxs)[i] =
        pack_h4(make_float4(v.x * ds, v.y * ds, v.z * ds, v.w * ds));
}

// ================= fused SpMV + Chebyshev combine (fp16 gather) ============
// Half-warp per node: 16 lanes x 4 halfs (uint2) cover the 128B fp16 row.

__device__ __forceinline__ void acc_h4(float4& a, uint2 u) {
    __half2 h0 = *reinterpret_cast<__half2*>(&u.x);
    __half2 h1 = *reinterpret_cast<__half2*>(&u.y);
    float2 f0 = __half22float2(h0);
    float2 f1 = __half22float2(h1);
    a.x += f0.x; a.y += f0.y; a.z += f1.x; a.w += f1.y;
}

template <int STEP>
__global__ void k_spmv(const __half* __restrict__ xin, __half* __restrict__ xout,
                       const float* __restrict__ x0, const float* __restrict__ lam, int N) {
    int lane = threadIdx.x & 31;
    int gw = (blockIdx.x * blockDim.x + threadIdx.x) >> 5;
    int node = gw * 2 + (lane >> 4);
    int q = lane & 15;
    if (node >= N) return;

    int beg = g_rowptr[node];
    int end = g_rowptr[node + 1];
    float4 acc = make_float4(0.f, 0.f, 0.f, 0.f);
    int e = beg;
    for (; e + 4 <= end; e += 4) {
        int s0 = g_csrc[e];
        int s1 = g_csrc[e + 1];
        int s2 = g_csrc[e + 2];
        int s3 = g_csrc[e + 3];
        uint2 u0 = reinterpret_cast<const uint2*>(xin + (size_t)s0 * F)[q];
        uint2 u1 = reinterpret_cast<const uint2*>(xin + (size_t)s1 * F)[q];
        uint2 u2 = reinterpret_cast<const uint2*>(xin + (size_t)s2 * F)[q];
        uint2 u3 = reinterpret_cast<const uint2*>(xin + (size_t)s3 * F)[q];
        acc_h4(acc, u0); acc_h4(acc, u1); acc_h4(acc, u2); acc_h4(acc, u3);
    }
    for (; e < end; e++) {
        int s = g_csrc[e];
        uint2 u = reinterpret_cast<const uint2*>(xin + (size_t)s * F)[q];
        acc_h4(acc, u);
    }

    float ds = g_dsqrt[node];
    float re = 2.0f / lam[0];
    float4 out;
    if (STEP == 1) {
        float4 c = reinterpret_cast<const float4*>(x0 + (size_t)node * F)[q];
        float ca = -re, cc = re - 1.0f;
        out.x = ca * (acc.x * ds) + cc * c.x;
        out.y = ca * (acc.y * ds) + cc * c.y;
        out.z = ca * (acc.z * ds) + cc * c.z;
        out.w = ca * (acc.w * ds) + cc * c.w;
    } else {
        float4 c = reinterpret_cast<const float4*>(g_Xt + (size_t)node * OUTF + (STEP - 1) * F)[q];
        float4 p = reinterpret_cast<const float4*>(g_Xt + (size_t)node * OUTF + (STEP - 2) * F)[q];
        float ca = -2.0f * re, cc = 2.0f * (re - 1.0f);
        out.x = ca * (acc.x * ds) + cc * c.x - p.x;
        out.y = ca * (acc.y * ds) + cc * c.y - p.y;
        out.z = ca * (acc.z * ds) + cc * c.z - p.z;
        out.w = ca * (acc.w * ds) + cc * c.w - p.w;
    }
    reinterpret_cast<uint2*>(g_Xh + (size_t)node * OUTF + STEP * F)[q] = pack_h4(out);
    if (STEP < 3) {
        reinterpret_cast<float4*>(g_Xt + (size_t)node * OUTF + STEP * F)[q] = out;
        reinterpret_cast<uint2*>(xout + (size_t)node * F)[q] =
            pack_h4(make_float4(out.x * ds, out.y * ds, out.z * ds, out.w * ds));
    }
}

// ===== cp.async-pipelined fp16 mma GEMM: out = relu(Xh @ Wh^T + b) =====

#define BM 128
#define BN 128
#define BK2 32
#define LDH 40
#define A2_BYTES (BM * LDH * 2)
#define B2_BYTES (BN * LDH * 2)
#define STG2 (A2_BYTES + B2_BYTES)
#define GST 3
#define G_SMEM2 (STG2 * GST)

__device__ __forceinline__ void cp16(uint32_t d, const void* s, int szb) {
    asm volatile("cp.async.cg.shared.global [%0], [%1], 16, %2;"
                 :: "r"(d), "l"(s), "r"(szb));
}

__device__ __forceinline__ void g_stage2(uint32_t sb, int slot, int bm, int bn,
                                         int k0, int M, int tid) {
    uint32_t ab = sb + slot * STG2;
    uint32_t bb = ab + A2_BYTES;
#pragma unroll
    for (int t = 0; t < 4; t++) {
        int c = tid + t * 256;
        if (c < 512) {
            int row = c >> 2;
            int part = c & 3;
            int sz = (bm + row < M) ? 16 : 0;
            cp16(ab + row * (LDH * 2) + part * 16,
                 g_Xh + (size_t)(bm + row) * OUTF + k0 + part * 8, sz);
        } else {
            int c2 = c - 512;
            int nr = c2 >> 2;
            int part = c2 & 3;
            cp16(bb + nr * (LDH * 2) + part * 16,
                 g_Wh + (size_t)(bn + nr) * OUTF + k0 + part * 8, 16);
        }
    }
    asm volatile("cp.async.commit_group;" ::: "memory");
}

__device__ __forceinline__ void mma_f16(float* c, const uint32_t* a, const uint32_t* b) {
    asm volatile(
        "mma.sync.aligned.m16n8k16.row.col.f32.f16.f16.f32 "
        "{%0,%1,%2,%3}, {%4,%5,%6,%7}, {%8,%9}, {%0,%1,%2,%3};"
        : "+f"(c[0]), "+f"(c[1]), "+f"(c[2]), "+f"(c[3])
        : "r"(a[0]), "r"(a[1]), "r"(a[2]), "r"(a[3]), "r"(b[0]), "r"(b[1]));
}

__global__ __launch_bounds__(256, 2)
void k_gemm_h(const float* __restrict__ bias, float* __restrict__ out, int M) {
    extern __shared__ char smem[];
    uint32_t sb = (uint32_t)__cvta_generic_to_shared(smem);

    int tid = threadIdx.x;
    int lane = tid & 31;
    int wid = tid >> 5;
    int wm = wid & 1;
    int wn = wid >> 1;
    int g = lane >> 2;
    int ti = lane & 3;
    int bm = blockIdx.x * BM;
    int bn = blockIdx.y * BN;

    float acc[4][4][4];
#pragma unroll
    for (int mf = 0; mf < 4; mf++)
#pragma unroll
        for (int nf = 0; nf < 4; nf++)
#pragma unroll
            for (int r = 0; r < 4; r++) acc[mf][nf][r] = 0.f;

    g_stage2(sb, 0, bm, bn, 0, M, tid);
    g_stage2(sb, 1, bm, bn, BK2, M, tid);

    const int NT = OUTF / BK2;   // 8
#pragma unroll 1
    for (int t = 0; t < NT; t++) {
        asm volatile("cp.async.wait_group 1;" ::: "memory");
        __syncthreads();
        if (t + 2 < NT)
            g_stage2(sb, (t + 2) % GST, bm, bn, (t + 2) * BK2, M, tid);
        else
            asm volatile("cp.async.commit_group;" ::: "memory");

        int slot = t % GST;
        const __half* Asl = reinterpret_cast<const __half*>(smem + slot * STG2);
        const __half* Bsl = reinterpret_cast<const __half*>(smem + slot * STG2 + A2_BYTES);

#pragma unroll
        for (int ks = 0; ks < 2; ks++) {
            int ko = ks * 16;
            uint32_t af[4][4], bf[4][2];
#pragma unroll
            for (int mf = 0; mf < 4; mf++) {
                int m = wm * 64 + mf * 16 + g;
                af[mf][0] = *reinterpret_cast<const uint32_t*>(Asl + m * LDH + ko + 2 * ti);
                af[mf][1] = *reinterpret_cast<const uint32_t*>(Asl + (m + 8) * LDH + ko + 2 * ti);
                af[mf][2] = *reinterpret_cast<const uint32_t*>(Asl + m * LDH + ko + 2 * ti + 8);
                af[mf][3] = *reinterpret_cast<const uint32_t*>(Asl + (m + 8) * LDH + ko + 2 * ti + 8);
            }
#pragma unroll
            for (int nf = 0; nf < 4; nf++) {
                int n = wn * 32 + nf * 8 + g;
                bf[nf][0] = *reinterpret_cast<const uint32_t*>(Bsl + n * LDH + ko + 2 * ti);
                bf[nf][1] = *reinterpret_cast<const uint32_t*>(Bsl + n * LDH + ko + 2 * ti + 8);
            }
#pragma unroll
            for (int mf = 0; mf < 4; mf++)
#pragma unroll
                for (int nf = 0; nf < 4; nf++)
                    mma_f16(acc[mf][nf], af[mf], bf[nf]);
        }
    }

#pragma unroll
    for (int mf = 0; mf < 4; mf++) {
        int row0 = bm + wm * 64 + mf * 16 + g;
#pragma unroll
        for (int nf = 0; nf < 4; nf++) {
            int col = bn + wn * 32 + nf * 8 + ti * 2;
            float2 bb = *reinterpret_cast<const float2*>(bias + col);
            if (row0 < M) {
                float2 o;
                o.x = fmaxf(acc[mf][nf][0] + bb.x, 0.f);
                o.y = fmaxf(acc[mf][nf][1] + bb.y, 0.f);
                *reinterpret_cast<float2*>(out + (size_t)row0 * OUTF + col) = o;
            }
            if (row0 + 8 < M) {
                float2 o;
                o.x = fmaxf(acc[mf][nf][2] + bb.x, 0.f);
                o.y = fmaxf(acc[mf][nf][3] + bb.y, 0.f);
                *reinterpret_cast<float2*>(out + (size_t)(row0 + 8) * OUTF + col) = o;
            }
        }
    }
}

// ================= launch =================

extern "C" void kernel_launch(void* const* d_in, const int* in_sizes, int n_in,
                              void* d_out, int out_size) {
    const float* signal = (const float*)d_in[0];
    const int*   src    = (const int*)d_in[1];
    const int*   dst    = (const int*)d_in[2];
    const float* lam    = (const float*)d_in[3];
    const float* Wm     = (const float*)d_in[4];
    const float* bias   = (const float*)d_in[5];
    float*       out    = (float*)d_out;

    int N = in_sizes[0] / F;
    int E = in_sizes[1];
    int n16 = N * F4;

    cudaFuncSetAttribute(k_gemm_h, cudaFuncAttributeMaxDynamicSharedMemorySize, G_SMEM2);

    k_zero_deg<<<(N + 255) / 256, 256>>>(N);
    k_hist<<<(E + 255) / 256, 256>>>(dst, E);

    k_scan1<<<NBLK, SCAN_B>>>(N);
    k_scan2<<<1, 128>>>();
    k_scan3<<<(N + 255) / 256, 256>>>(N, E);     // + dsqrt fused
    k_fill<<<(E + 255) / 256, 256>>>(src, dst, E);

    k_prep<<<(n16 + 255) / 256, 256>>>(signal, n16);
    k_wt<<<OUTF, OUTF>>>(Wm);

    __half* xs_ping = nullptr;
    __half* xs_pong = nullptr;
    cudaGetSymbolAddress((void**)&xs_ping, g_hxs);
    cudaGetSymbolAddress((void**)&xs_pong, g_hxs2);

    int nb_spmv = (N * 16 + 255) / 256;
    k_spmv<1><<<nb_spmv, 256>>>(xs_ping, xs_pong, signal, lam, N);
    k_spmv<2><<<nb_spmv, 256>>>(xs_pong, xs_ping, signal, lam, N);
    k_spmv<3><<<nb_spmv, 256>>>(xs_ping, xs_pong, signal, lam, N);

    dim3 gg((N + BM - 1) / BM, OUTF / BN);
    k_gemm_h<<<gg, 256, G_SMEM2>>>(bias, out, N);
}

// round 13
// speedup vs baseline: 2.8750x; 1.0174x over previous
#include <cuda_runtime.h>
#include <cuda_fp16.h>
#include <cstdint>

#define NN      50000
#define NE      800000
#define F       64
#define F4      16
#define OUTF    256
#define SCAN_B  512
#define NBLK    ((NN + SCAN_B - 1) / SCAN_B)   // 98

// -------- scratch (device globals; no allocation allowed) --------
__device__ float g_dsqrt[NN];
__device__ int   g_deg[NN];
__device__ int   g_rowptr[NN + 1];
__device__ int   g_cur[NN];
__device__ int   g_bsum[NBLK];
__device__ int   g_csrc[NE];
__device__ __half g_hxs[NN * F];                 // ping (fp16 normalized features)
__device__ __half g_hxs2[NN * F];                // pong
__device__ float g_Xt[(size_t)NN * OUTF];        // fp32 concat (recurrence reads blocks 0..2)
__device__ __half g_Xh[(size_t)NN * OUTF];       // fp16 concat (GEMM A operand)
__device__ __half g_Wh[OUTF * OUTF];             // W transposed: g_Wh[n*256+k] = W[k][n], fp16

// ================= init: zero_deg + W->fp16 transpose (fused) =================

__global__ void k_init(const float* __restrict__ Wm, int n) {
    int b = blockIdx.x;
    int t = threadIdx.x;
    if (b < OUTF) {
        g_Wh[(size_t)b * OUTF + t] = __float2half_rn(Wm[(size_t)t * OUTF + b]);
    } else {
        int i = (b - OUTF) * 256 + t;
        if (i < n) g_deg[i] = 0;
    }
}

__global__ void k_hist(const int* __restrict__ dst, int E) {
    int i = blockIdx.x * blockDim.x + threadIdx.x;
    if (i < E) atomicAdd(&g_deg[dst[i]], 1);
}

// ================= CSR scan =================

__global__ void k_scan1(int n) {
    __shared__ int ws[16];
    int t = threadIdx.x;
    int lane = t & 31;
    int w = t >> 5;
    int i = blockIdx.x * SCAN_B + t;
    int v = (i < n) ? g_deg[i] : 0;
    int x = v;
#pragma unroll
    for (int o = 1; o < 32; o <<= 1) {
        int y = __shfl_up_sync(0xFFFFFFFFu, x, o);
        if (lane >= o) x += y;
    }
    if (lane == 31) ws[w] = x;
    __syncthreads();
    if (w == 0) {
        int s = (lane < 16) ? ws[lane] : 0;
#pragma unroll
        for (int o = 1; o < 16; o <<= 1) {
            int y = __shfl_up_sync(0xFFFFFFFFu, s, o);
            if (lane >= o) s += y;
        }
        if (lane < 16) ws[lane] = s;
    }
    __syncthreads();
    int base = (w > 0) ? ws[w - 1] : 0;
    int incl = base + x;
    if (i < n) g_rowptr[i] = incl - v;
    if (t == SCAN_B - 1) g_bsum[blockIdx.x] = incl;
}

// Fused scan2+scan3+dsqrt. Block = 256 threads; only t<128 touch sh[] (smem is
// 128 ints); ALL threads hit every __syncthreads (no divergent barriers).
__global__ void k_scan23(int n, int E) {
    __shared__ int sh[128];
    int t = threadIdx.x;
    int v = (t < NBLK) ? g_bsum[t] : 0;
    if (t < 128) sh[t] = v;
    __syncthreads();
#pragma unroll
    for (int off = 1; off < 128; off <<= 1) {
        int x = (t >= off && t < 128) ? sh[t - off] : 0;
        __syncthreads();
        if (t < 128) sh[t] += x;
        __syncthreads();
    }
    if (t < NBLK) sh[t] -= v;   // inclusive -> exclusive, own slot only
    __syncthreads();

    int i = blockIdx.x * blockDim.x + t;
    if (i < n) {
        int r = g_rowptr[i] + sh[i / SCAN_B];
        g_rowptr[i] = r;
        g_cur[i] = r;
        int d = g_deg[i];
        if (d < 1) d = 1;
        g_dsqrt[i] = rsqrtf((float)d);
    }
    if (i == 0) g_rowptr[n] = E;
}

// ================= fp16 pack helpers =================

__device__ __forceinline__ uint2 pack_h4(float4 v) {
    __half2 h0 = __floats2half2_rn(v.x, v.y);
    __half2 h1 = __floats2half2_rn(v.z, v.w);
    uint2 u;
    u.x = *reinterpret_cast<unsigned*>(&h0);
    u.y = *reinterpret_cast<unsigned*>(&h1);
    return u;
}

// ================= fill + prep (fused, independent outputs) =================

__global__ void k_fillprep(const int* __restrict__ src, const int* __restrict__ dst,
                           const float* __restrict__ x0, int E, int Eb, int n16) {
    int b = blockIdx.x;
    int t = threadIdx.x;
    if (b < Eb) {
        int i = b * 256 + t;
        if (i < E) {
            int pos = atomicAdd(&g_cur[dst[i]], 1);
            g_csrc[pos] = src[i];
        }
    } else {
        int i = (b - Eb) * 256 + t;
        if (i >= n16) return;
        int node = i >> 4;
        int q = i & 15;
        float ds = g_dsqrt[node];
        float4 v = reinterpret_cast<const float4*>(x0)[i];
        reinterpret_cast<float4*>(g_Xt + (size_t)node * OUTF)[q] = v;
        reinterpret_cast<uint2*>(g_Xh + (size_t)node * OUTF)[q] = pack_h4(v);
        reinterpret_cast<uint2*>(g_hxs)[i] =
            pack_h4(make_float4(v.x * ds, v.y * ds, v.z * ds, v.w * ds));
    }
}

// ================= fused SpMV + Chebyshev combine (fp16 gather) ============

__device__ __forceinline__ void acc_h4(float4& a, uint2 u) {
    __half2 h0 = *reinterpret_cast<__half2*>(&u.x);
    __half2 h1 = *reinterpret_cast<__half2*>(&u.y);
    float2 f0 = __half22float2(h0);
    float2 f1 = __half22float2(h1);
    a.x += f0.x; a.y += f0.y; a.z += f1.x; a.w += f1.y;
}

template <int STEP>
__global__ void k_spmv(const __half* __restrict__ xin, __half* __restrict__ xout,
                       const float* __restrict__ x0, const float* __restrict__ lam, int N) {
    int lane = threadIdx.x & 31;
    int gw = (blockIdx.x * blockDim.x + threadIdx.x) >> 5;
    int node = gw * 2 + (lane >> 4);
    int q = lane & 15;
    if (node >= N) return;

    int beg = g_rowptr[node];
    int end = g_rowptr[node + 1];
    float4 acc = make_float4(0.f, 0.f, 0.f, 0.f);
    int e = beg;
    for (; e + 8 <= end; e += 8) {
        uint2 u0 = reinterpret_cast<const uint2*>(xin + (size_t)g_csrc[e    ] * F)[q];
        uint2 u1 = reinterpret_cast<const uint2*>(xin + (size_t)g_csrc[e + 1] * F)[q];
        uint2 u2 = reinterpret_cast<const uint2*>(xin + (size_t)g_csrc[e + 2] * F)[q];
        uint2 u3 = reinterpret_cast<const uint2*>(xin + (size_t)g_csrc[e + 3] * F)[q];
        uint2 u4 = reinterpret_cast<const uint2*>(xin + (size_t)g_csrc[e + 4] * F)[q];
        uint2 u5 = reinterpret_cast<const uint2*>(xin + (size_t)g_csrc[e + 5] * F)[q];
        uint2 u6 = reinterpret_cast<const uint2*>(xin + (size_t)g_csrc[e + 6] * F)[q];
        uint2 u7 = reinterpret_cast<const uint2*>(xin + (size_t)g_csrc[e + 7] * F)[q];
        acc_h4(acc, u0); acc_h4(acc, u1); acc_h4(acc, u2); acc_h4(acc, u3);
        acc_h4(acc, u4); acc_h4(acc, u5); acc_h4(acc, u6); acc_h4(acc, u7);
    }
    for (; e < end; e++) {
        uint2 u = reinterpret_cast<const uint2*>(xin + (size_t)g_csrc[e] * F)[q];
        acc_h4(acc, u);
    }

    float ds = g_dsqrt[node];
    float re = 2.0f / lam[0];
    float4 out;
    if (STEP == 1) {
        float4 c = reinterpret_cast<const float4*>(x0 + (size_t)node * F)[q];
        float ca = -re, cc = re - 1.0f;
        out.x = ca * (acc.x * ds) + cc * c.x;
        out.y = ca * (acc.y * ds) + cc * c.y;
        out.z = ca * (acc.z * ds) + cc * c.z;
        out.w = ca * (acc.w * ds) + cc * c.w;
    } else {
        float4 c = reinterpret_cast<const float4*>(g_Xt + (size_t)node * OUTF + (STEP - 1) * F)[q];
        float4 p = reinterpret_cast<const float4*>(g_Xt + (size_t)node * OUTF + (STEP - 2) * F)[q];
        float ca = -2.0f * re, cc = 2.0f * (re - 1.0f);
        out.x = ca * (acc.x * ds) + cc * c.x - p.x;
        out.y = ca * (acc.y * ds) + cc * c.y - p.y;
        out.z = ca * (acc.z * ds) + cc * c.z - p.z;
        out.w = ca * (acc.w * ds) + cc * c.w - p.w;
    }
    reinterpret_cast<uint2*>(g_Xh + (size_t)node * OUTF + STEP * F)[q] = pack_h4(out);
    if (STEP < 3) {
        reinterpret_cast<float4*>(g_Xt + (size_t)node * OUTF + STEP * F)[q] = out;
        reinterpret_cast<uint2*>(xout + (size_t)node * F)[q] =
            pack_h4(make_float4(out.x * ds, out.y * ds, out.z * ds, out.w * ds));
    }
}

// ===== cp.async-pipelined fp16 mma GEMM: out = relu(Xh @ Wh^T + b) =====

#define BM 128
#define BN 128
#define BK2 32
#define LDH 40
#define A2_BYTES (BM * LDH * 2)
#define B2_BYTES (BN * LDH * 2)
#define STG2 (A2_BYTES + B2_BYTES)
#define GST 3
#define G_SMEM2 (STG2 * GST)

__device__ __forceinline__ void cp16(uint32_t d, const void* s, int szb) {
    asm volatile("cp.async.cg.shared.global [%0], [%1], 16, %2;"
                 :: "r"(d), "l"(s), "r"(szb));
}

__device__ __forceinline__ void g_stage2(uint32_t sb, int slot, int bm, int bn,
                                         int k0, int M, int tid) {
    uint32_t ab = sb + slot * STG2;
    uint32_t bb = ab + A2_BYTES;
#pragma unroll
    for (int t = 0; t < 4; t++) {
        int c = tid + t * 256;
        if (c < 512) {
            int row = c >> 2;
            int part = c & 3;
            int sz = (bm + row < M) ? 16 : 0;
            cp16(ab + row * (LDH * 2) + part * 16,
                 g_Xh + (size_t)(bm + row) * OUTF + k0 + part * 8, sz);
        } else {
            int c2 = c - 512;
            int nr = c2 >> 2;
            int part = c2 & 3;
            cp16(bb + nr * (LDH * 2) + part * 16,
                 g_Wh + (size_t)(bn + nr) * OUTF + k0 + part * 8, 16);
        }
    }
    asm volatile("cp.async.commit_group;" ::: "memory");
}

__device__ __forceinline__ void mma_f16(float* c, const uint32_t* a, const uint32_t* b) {
    asm volatile(
        "mma.sync.aligned.m16n8k16.row.col.f32.f16.f16.f32 "
        "{%0,%1,%2,%3}, {%4,%5,%6,%7}, {%8,%9}, {%0,%1,%2,%3};"
        : "+f"(c[0]), "+f"(c[1]), "+f"(c[2]), "+f"(c[3])
        : "r"(a[0]), "r"(a[1]), "r"(a[2]), "r"(a[3]), "r"(b[0]), "r"(b[1]));
}

__global__ __launch_bounds__(256, 2)
void k_gemm_h(const float* __restrict__ bias, float* __restrict__ out, int M) {
    extern __shared__ char smem[];
    uint32_t sb = (uint32_t)__cvta_generic_to_shared(smem);

    int tid = threadIdx.x;
    int lane = tid & 31;
    int wid = tid >> 5;
    int wm = wid & 1;
    int wn = wid >> 1;
    int g = lane >> 2;
    int ti = lane & 3;
    int bm = blockIdx.x * BM;
    int bn = blockIdx.y * BN;

    float acc[4][4][4];
#pragma unroll
    for (int mf = 0; mf < 4; mf++)
#pragma unroll
        for (int nf = 0; nf < 4; nf++)
#pragma unroll
            for (int r = 0; r < 4; r++) acc[mf][nf][r] = 0.f;

    g_stage2(sb, 0, bm, bn, 0, M, tid);
    g_stage2(sb, 1, bm, bn, BK2, M, tid);

    const int NT = OUTF / BK2;   // 8
#pragma unroll 1
    for (int t = 0; t < NT; t++) {
        asm volatile("cp.async.wait_group 1;" ::: "memory");
        __syncthreads();
        if (t + 2 < NT)
            g_stage2(sb, (t + 2) % GST, bm, bn, (t + 2) * BK2, M, tid);
        else
            asm volatile("cp.async.commit_group;" ::: "memory");

        int slot = t % GST;
        const __half* Asl = reinterpret_cast<const __half*>(smem + slot * STG2);
        const __half* Bsl = reinterpret_cast<const __half*>(smem + slot * STG2 + A2_BYTES);

#pragma unroll
        for (int ks = 0; ks < 2; ks++) {
            int ko = ks * 16;
            uint32_t af[4][4], bf[4][2];
#pragma unroll
            for (int mf = 0; mf < 4; mf++) {
                int m = wm * 64 + mf * 16 + g;
                af[mf][0] = *reinterpret_cast<const uint32_t*>(Asl + m * LDH + ko + 2 * ti);
                af[mf][1] = *reinterpret_cast<const uint32_t*>(Asl + (m + 8) * LDH + ko + 2 * ti);
                af[mf][2] = *reinterpret_cast<const uint32_t*>(Asl + m * LDH + ko + 2 * ti + 8);
                af[mf][3] = *reinterpret_cast<const uint32_t*>(Asl + (m + 8) * LDH + ko + 2 * ti + 8);
            }
#pragma unroll
            for (int nf = 0; nf < 4; nf++) {
                int n = wn * 32 + nf * 8 + g;
                bf[nf][0] = *reinterpret_cast<const uint32_t*>(Bsl + n * LDH + ko + 2 * ti);
                bf[nf][1] = *reinterpret_cast<const uint32_t*>(Bsl + n * LDH + ko + 2 * ti + 8);
            }
#pragma unroll
            for (int mf = 0; mf < 4; mf++)
#pragma unroll
                for (int nf = 0; nf < 4; nf++)
                    mma_f16(acc[mf][nf], af[mf], bf[nf]);
        }
    }

#pragma unroll
    for (int mf = 0; mf < 4; mf++) {
        int row0 = bm + wm * 64 + mf * 16 + g;
#pragma unroll
        for (int nf = 0; nf < 4; nf++) {
            int col = bn + wn * 32 + nf * 8 + ti * 2;
            float2 bb = *reinterpret_cast<const float2*>(bias + col);
            if (row0 < M) {
                float2 o;
                o.x = fmaxf(acc[mf][nf][0] + bb.x, 0.f);
                o.y = fmaxf(acc[mf][nf][1] + bb.y, 0.f);
                *reinterpret_cast<float2*>(out + (size_t)row0 * OUTF + col) = o;
            }
            if (row0 + 8 < M) {
                float2 o;
                o.x = fmaxf(acc[mf][nf][2] + bb.x, 0.f);
                o.y = fmaxf(acc[mf][nf][3] + bb.y, 0.f);
                *reinterpret_cast<float2*>(out + (size_t)(row0 + 8) * OUTF + col) = o;
            }
        }
    }
}

// ================= launch =================

extern "C" void kernel_launch(void* const* d_in, const int* in_sizes, int n_in,
                              void* d_out, int out_size) {
    const float* signal = (const float*)d_in[0];
    const int*   src    = (const int*)d_in[1];
    const int*   dst    = (const int*)d_in[2];
    const float* lam    = (const float*)d_in[3];
    const float* Wm     = (const float*)d_in[4];
    const float* bias   = (const float*)d_in[5];
    float*       out    = (float*)d_out;

    int N = in_sizes[0] / F;
    int E = in_sizes[1];
    int n16 = N * F4;
    int Eb = (E + 255) / 256;
    int Pb = (n16 + 255) / 256;
    int Zb = (N + 255) / 256;

    cudaFuncSetAttribute(k_gemm_h, cudaFuncAttributeMaxDynamicSharedMemorySize, G_SMEM2);

    k_init<<<OUTF + Zb, 256>>>(Wm, N);
    k_hist<<<Eb, 256>>>(dst, E);
    k_scan1<<<NBLK, SCAN_B>>>(N);
    k_scan23<<<Zb, 256>>>(N, E);
    k_fillprep<<<Eb + Pb, 256>>>(src, dst, signal, E, Eb, n16);

    __half* xs_ping = nullptr;
    __half* xs_pong = nullptr;
    cudaGetSymbolAddress((void**)&xs_ping, g_hxs);
    cudaGetSymbolAddress((void**)&xs_pong, g_hxs2);

    int nb_spmv = (N * 16 + 255) / 256;
    k_spmv<1><<<nb_spmv, 256>>>(xs_ping, xs_pong, signal, lam, N);
    k_spmv<2><<<nb_spmv, 256>>>(xs_pong, xs_ping, signal, lam, N);
    k_spmv<3><<<nb_spmv, 256>>>(xs_ping, xs_pong, signal, lam, N);

    dim3 gg((N + BM - 1) / BM, OUTF / BN);
    k_gemm_h<<<gg, 256, G_SMEM2>>>(bias, out, N);
}